// round 5
// baseline (speedup 1.0000x reference)
#include <cuda_runtime.h>
#include <cstdint>

#define BB 4
#define NT 2048
#define DD 512
#define HH 8
#define DHH 64
#define INNER 512
#define QKVC 1536
#define ATT_SCALE 0.125f
#define NJT 64            // 2048/32 j-tiles

// Scratch (device globals — no cudaMalloc allowed)
static __device__ float g_qkv[(size_t)BB * NT * QKVC];   // tf32-rounded
static __device__ float g_obuf[(size_t)BB * NT * INNER];

// ---------------------------------------------------------------------------
// helpers
// ---------------------------------------------------------------------------
__device__ __forceinline__ uint32_t f2tf32(float x) {
    uint32_t r;
    asm("cvt.rna.tf32.f32 %0, %1;" : "=r"(r) : "f"(x));
    return r;
}

__device__ __forceinline__ uint32_t smaddr(const void* p) {
    uint32_t a;
    asm("{.reg .u64 t; cvta.to.shared.u64 t, %1; cvt.u32.u64 %0, t;}"
        : "=r"(a) : "l"(p));
    return a;
}

__device__ __forceinline__ void mma_tf32(float c[4], uint32_t a0, uint32_t a1,
                                         uint32_t a2, uint32_t a3,
                                         uint32_t b0, uint32_t b1) {
    asm volatile(
        "mma.sync.aligned.m16n8k8.row.col.f32.tf32.tf32.f32 "
        "{%0,%1,%2,%3}, {%4,%5,%6,%7}, {%8,%9}, {%0,%1,%2,%3};"
        : "+f"(c[0]), "+f"(c[1]), "+f"(c[2]), "+f"(c[3])
        : "r"(a0), "r"(a1), "r"(a2), "r"(a3), "r"(b0), "r"(b1));
}

__device__ __forceinline__ void bulk_cp(uint32_t dst, const void* src,
                                        uint32_t bytes, uint32_t mbar) {
    asm volatile(
        "cp.async.bulk.shared::cta.global.mbarrier::complete_tx::bytes "
        "[%0], [%1], %2, [%3];"
        :: "r"(dst), "l"(src), "r"(bytes), "r"(mbar) : "memory");
}

__device__ __forceinline__ void mbar_expect(uint32_t mbar, uint32_t bytes) {
    asm volatile("mbarrier.arrive.expect_tx.shared.b64 _, [%0], %1;"
                 :: "r"(mbar), "r"(bytes) : "memory");
}

__device__ __forceinline__ void mbar_wait(uint32_t mbar, uint32_t parity) {
    uint32_t done;
    do {
        asm volatile(
            "{.reg .pred p; "
            "mbarrier.try_wait.parity.acquire.cta.shared::cta.b64 p, [%1], %2, 0x989680; "
            "selp.b32 %0,1,0,p;}"
            : "=r"(done) : "r"(mbar), "r"(parity) : "memory");
    } while (!done);
}

// ---------------------------------------------------------------------------
// SGEMM: 64x64 tile, K-step 16, 256 thr, 4x4 micro — now double-buffered smem
// with register prefetch (removes exposed LDG latency of the R1 version).
// TFR: round outputs to tf32 (rna) for tensor-core consumption downstream.
// ---------------------------------------------------------------------------
template <bool HAS_BIAS, bool TFR>
__global__ __launch_bounds__(256) void sgemm_kernel(
    const float* __restrict__ A, const float* __restrict__ Bm,
    const float* __restrict__ bias, float* __restrict__ C,
    int M, int Ncols, int K)
{
    __shared__ float As[2][16][68];
    __shared__ float Bs[2][16][68];
    const int tid = threadIdx.x;
    const int tx = tid & 15, ty = tid >> 4;
    const int m0 = blockIdx.y << 6, n0 = blockIdx.x << 6;
    const int ar = tid >> 2, ac4 = (tid & 3) << 2;
    const int bkr = tid >> 4, bc = (tid & 15) << 2;

    const float* Aptr = A + (size_t)(m0 + ar) * K + ac4;
    const float* Bptr = Bm + (size_t)bkr * Ncols + n0 + bc;

    float acc[4][4] = {};
    float4 a = *(const float4*)Aptr;
    float4 bv4l = *(const float4*)Bptr;

    const int nk = K >> 4;
#define SG_STORE(buf)                                                       \
    do {                                                                    \
        As[buf][ac4 + 0][ar] = a.x;                                         \
        As[buf][ac4 + 1][ar] = a.y;                                         \
        As[buf][ac4 + 2][ar] = a.z;                                         \
        As[buf][ac4 + 3][ar] = a.w;                                         \
        *(float4*)&Bs[buf][bkr][bc] = bv4l;                                 \
    } while (0)

    SG_STORE(0);
    __syncthreads();

    for (int t = 0; t < nk; t++) {
        const int buf = t & 1;
        if (t + 1 < nk) {
            const int k0 = (t + 1) << 4;
            a = *(const float4*)(Aptr + k0);
            bv4l = *(const float4*)(Bptr + (size_t)k0 * Ncols);
        }
#pragma unroll
        for (int kk = 0; kk < 16; kk++) {
            float av[4], bv[4];
            *(float4*)av = *(const float4*)&As[buf][kk][ty << 2];
            *(float4*)bv = *(const float4*)&Bs[buf][kk][tx << 2];
#pragma unroll
            for (int i = 0; i < 4; i++)
#pragma unroll
                for (int j = 0; j < 4; j++)
                    acc[i][j] = fmaf(av[i], bv[j], acc[i][j]);
        }
        if (t + 1 < nk) SG_STORE(buf ^ 1);
        __syncthreads();
    }
#undef SG_STORE

    float4 bb = make_float4(0.f, 0.f, 0.f, 0.f);
    if (HAS_BIAS) bb = *(const float4*)(bias + n0 + (tx << 2));
#pragma unroll
    for (int i = 0; i < 4; i++) {
        float4 o;
        o.x = acc[i][0] + bb.x;
        o.y = acc[i][1] + bb.y;
        o.z = acc[i][2] + bb.z;
        o.w = acc[i][3] + bb.w;
        if (TFR) {
            o.x = __uint_as_float(f2tf32(o.x));
            o.y = __uint_as_float(f2tf32(o.y));
            o.z = __uint_as_float(f2tf32(o.z));
            o.w = __uint_as_float(f2tf32(o.w));
        }
        *(float4*)(C + (size_t)(m0 + (ty << 2) + i) * Ncols + n0 + (tx << 2)) = o;
    }
}

// ---------------------------------------------------------------------------
// Fused flash attention, tf32 mma + DOUBLE-BUFFERED bulk-async staging.
// i-tile 128, j-tile 32, 256 thr (8 warps), warp = 16 i-rows x full j/d.
// smem (floats):
//   QF  [8 wtile][8 kk][128]  Q A-fragments                 32 KB
//   KS  2 x [32][68]                                        17 KB
//   VS  2 x [32][72]                                        18 KB
//   CD  2 x [3][128][36]                                   108 KB
//   PS  [8 w][16][36]                                       18 KB
//   2 mbarriers
// ---------------------------------------------------------------------------
#define QF0 0
#define KS_OFF 8192
#define KS_SZ 2176
#define VS_OFF 12544
#define VS_SZ 2304
#define CD_OFF 17152
#define CD_SZ 13824
#define PS_OFF 44800
#define SMF 49408
#define ATTN_SMEM_BYTES (SMF * 4 + 16)
#define TILE_BYTES 65536u   // K 8K + V 8K + CD 48K

__device__ __forceinline__ void issue_copy(int idx, int jn, int buf, int b,
                                           int h, int i0, const float* qkv,
                                           const float* cd, float* sm,
                                           uint32_t mbar) {
    if (idx < 32) {
        const float* src = qkv + ((size_t)(b * NT + jn + idx) * QKVC
                                  + INNER + h * DHH);
        bulk_cp(smaddr(sm + KS_OFF + buf * KS_SZ + idx * 68), src, 256u, mbar);
    } else if (idx < 64) {
        const int r = idx - 32;
        const float* src = qkv + ((size_t)(b * NT + jn + r) * QKVC
                                  + 2 * INNER + h * DHH);
        bulk_cp(smaddr(sm + VS_OFF + buf * VS_SZ + r * 72), src, 256u, mbar);
    } else {
        const int q = idx - 64, p = q >> 7, rl = q & 127;
        const float* src = cd + ((size_t)(b * 3 + p) * NT * NT
                                 + (size_t)(i0 + rl) * NT + jn);
        bulk_cp(smaddr(sm + CD_OFF + buf * CD_SZ + (p * 128 + rl) * 36),
                src, 128u, mbar);
    }
}

__global__ __launch_bounds__(256) void attn_kernel(
    const float* __restrict__ qkv, const float* __restrict__ cd,
    const float* __restrict__ rel_w, const float* __restrict__ rel_b,
    float* __restrict__ obuf)
{
    extern __shared__ float sm[];
    const int tid = threadIdx.x;
    const int lane = tid & 31, w = tid >> 5;
    const int g = lane >> 2, t = lane & 3;
    const int h = blockIdx.x & 7;
    const int i0 = (blockIdx.x >> 3) << 7;
    const int b = blockIdx.y;

    const uint32_t mbar0 = smaddr(sm + SMF);
    // per-thread copy assignment: idx1 = tid, idx2 = tid + 256 (tid < 192)
    const int idx1 = tid;
    const int idx2 = tid + 256;
    const uint32_t myBytes = (idx1 < 64 ? 256u : 128u)
                           + (tid < 192 ? (idx2 < 64 ? 256u : 128u) : 0u);

    if (tid == 0) {
        asm volatile("mbarrier.init.shared.b64 [%0], %1;"
                     :: "r"(mbar0), "r"(256u) : "memory");
        asm volatile("mbarrier.init.shared.b64 [%0], %1;"
                     :: "r"(mbar0 + 8), "r"(256u) : "memory");
        asm volatile("fence.proxy.async.shared::cta;" ::: "memory");
    }
    __syncthreads();

    // ---- prologue: stage tiles 0 (buf0) and 1 (buf1) ----
#pragma unroll
    for (int pt = 0; pt < 2; pt++) {
        const uint32_t mb = mbar0 + 8 * pt;
        mbar_expect(mb, myBytes);
        issue_copy(idx1, pt * 32, pt, b, h, i0, qkv, cd, sm, mb);
        if (tid < 192) issue_copy(idx2, pt * 32, pt, b, h, i0, qkv, cd, sm, mb);
    }

    // ---- stage Q into A-fragment layout (tf32-rounded already) ----
#pragma unroll
    for (int it = 0; it < 8; it++) {
        const int rowl = (tid >> 4) + it * 16;
        const int d4 = (tid & 15) << 2;
        float4 v = *(const float4*)(qkv + ((size_t)(b * NT + i0 + rowl) * QKVC
                                           + h * DHH + d4));
        const int wq = rowl >> 4, r16 = rowl & 15;
        const int gq = r16 & 7, hi = r16 >> 3;
        const float vv[4] = {v.x, v.y, v.z, v.w};
#pragma unroll
        for (int e = 0; e < 4; e++) {
            const int d = d4 + e;
            const int kk = d >> 3, tt = d & 3, shi = (d >> 2) & 1;
            sm[QF0 + ((wq * 8 + kk) << 7) + ((gq * 4 + tt) << 2) + hi + 2 * shi]
                = vv[e];
        }
    }
    __syncthreads();

    const float w0 = rel_w[h * 3 + 0], w1 = rel_w[h * 3 + 1], w2 = rel_w[h * 3 + 2];
    const float rb = rel_b[h];

    float m0 = -1e30f, m1 = -1e30f, l0 = 0.f, l1 = 0.f;
    float o[8][4];
#pragma unroll
    for (int dd = 0; dd < 8; dd++)
        o[dd][0] = o[dd][1] = o[dd][2] = o[dd][3] = 0.f;

    float* PSw = sm + PS_OFF + w * (16 * 36);

    for (int jt = 0; jt < NJT; jt++) {
        const int buf = jt & 1;
        const float* ks = sm + KS_OFF + buf * KS_SZ;
        const float* vs = sm + VS_OFF + buf * VS_SZ;
        const float* cdb = sm + CD_OFF + buf * CD_SZ;

        mbar_wait(mbar0 + 8 * buf, (jt >> 1) & 1);

        // ---- S = Q K^T ----
        float s_[4][4];
#pragma unroll
        for (int nn = 0; nn < 4; nn++)
            s_[nn][0] = s_[nn][1] = s_[nn][2] = s_[nn][3] = 0.f;
#pragma unroll
        for (int kk = 0; kk < 8; kk++) {
            const uint4 a = *(const uint4*)&sm[QF0 + ((w * 8 + kk) << 7) + (lane << 2)];
#pragma unroll
            for (int nn = 0; nn < 4; nn++) {
                const uint32_t b0 = __float_as_uint(ks[(nn * 8 + g) * 68 + kk * 8 + t]);
                const uint32_t b1 = __float_as_uint(ks[(nn * 8 + g) * 68 + kk * 8 + t + 4]);
                mma_tf32(s_[nn], a.x, a.y, a.z, a.w, b0, b1);
            }
        }

        // ---- bias + online softmax + P store ----
        const int rl0 = w * 16 + g, rl1 = rl0 + 8;
        float mx0 = -1e30f, mx1 = -1e30f;
#pragma unroll
        for (int nn = 0; nn < 4; nn++) {
            const int c = nn * 8 + 2 * t;
            const float2 p00 = *(const float2*)&cdb[rl0 * 36 + c];
            const float2 p01 = *(const float2*)&cdb[4608 + rl0 * 36 + c];
            const float2 p02 = *(const float2*)&cdb[9216 + rl0 * 36 + c];
            const float2 p10 = *(const float2*)&cdb[rl1 * 36 + c];
            const float2 p11 = *(const float2*)&cdb[4608 + rl1 * 36 + c];
            const float2 p12 = *(const float2*)&cdb[9216 + rl1 * 36 + c];
            s_[nn][0] = fmaf(s_[nn][0], ATT_SCALE, w0 * p00.x + w1 * p01.x + w2 * p02.x + rb);
            s_[nn][1] = fmaf(s_[nn][1], ATT_SCALE, w0 * p00.y + w1 * p01.y + w2 * p02.y + rb);
            s_[nn][2] = fmaf(s_[nn][2], ATT_SCALE, w0 * p10.x + w1 * p11.x + w2 * p12.x + rb);
            s_[nn][3] = fmaf(s_[nn][3], ATT_SCALE, w0 * p10.y + w1 * p11.y + w2 * p12.y + rb);
            mx0 = fmaxf(mx0, fmaxf(s_[nn][0], s_[nn][1]));
            mx1 = fmaxf(mx1, fmaxf(s_[nn][2], s_[nn][3]));
        }
#pragma unroll
        for (int off = 1; off <= 2; off <<= 1) {
            mx0 = fmaxf(mx0, __shfl_xor_sync(0xffffffffu, mx0, off));
            mx1 = fmaxf(mx1, __shfl_xor_sync(0xffffffffu, mx1, off));
        }
        const float mn0 = fmaxf(m0, mx0), mn1 = fmaxf(m1, mx1);
        const float fac0 = __expf(m0 - mn0), fac1 = __expf(m1 - mn1);
        m0 = mn0; m1 = mn1;
        float rs0 = 0.f, rs1 = 0.f;
#pragma unroll
        for (int nn = 0; nn < 4; nn++) {
            const float e0 = __expf(s_[nn][0] - mn0);
            const float e1 = __expf(s_[nn][1] - mn0);
            const float e2 = __expf(s_[nn][2] - mn1);
            const float e3 = __expf(s_[nn][3] - mn1);
            rs0 += e0 + e1; rs1 += e2 + e3;
            const int c = nn * 8 + 2 * t;
            *(uint2*)&PSw[rl0 % 16 * 0 + g * 36 + c] = make_uint2(f2tf32(e0), f2tf32(e1));
            *(uint2*)&PSw[(g + 8) * 36 + c] = make_uint2(f2tf32(e2), f2tf32(e3));
        }
#pragma unroll
        for (int off = 1; off <= 2; off <<= 1) {
            rs0 += __shfl_xor_sync(0xffffffffu, rs0, off);
            rs1 += __shfl_xor_sync(0xffffffffu, rs1, off);
        }
        l0 = l0 * fac0 + rs0;
        l1 = l1 * fac1 + rs1;
#pragma unroll
        for (int dd = 0; dd < 8; dd++) {
            o[dd][0] *= fac0; o[dd][1] *= fac0;
            o[dd][2] *= fac1; o[dd][3] *= fac1;
        }
        __syncwarp();   // P visible within warp (warp-private tile)

        // ---- O += P V ----
#pragma unroll
        for (int jj = 0; jj < 4; jj++) {
            const uint32_t a0 = __float_as_uint(PSw[g * 36 + jj * 8 + t]);
            const uint32_t a1 = __float_as_uint(PSw[(g + 8) * 36 + jj * 8 + t]);
            const uint32_t a2 = __float_as_uint(PSw[g * 36 + jj * 8 + t + 4]);
            const uint32_t a3 = __float_as_uint(PSw[(g + 8) * 36 + jj * 8 + t + 4]);
#pragma unroll
            for (int dd = 0; dd < 8; dd++) {
                const uint32_t b0 = __float_as_uint(vs[(jj * 8 + t) * 72 + dd * 8 + g]);
                const uint32_t b1 = __float_as_uint(vs[(jj * 8 + t + 4) * 72 + dd * 8 + g]);
                mma_tf32(o[dd], a0, a1, a2, a3, b0, b1);
            }
        }

        __syncthreads();   // buffer fully consumed by all warps

        if (jt + 2 < NJT) {
            const int jn = (jt + 2) * 32;
            const uint32_t mb = mbar0 + 8 * buf;
            mbar_expect(mb, myBytes);
            issue_copy(idx1, jn, buf, b, h, i0, qkv, cd, sm, mb);
            if (tid < 192) issue_copy(idx2, jn, buf, b, h, i0, qkv, cd, sm, mb);
        }
    }

    // ---- normalize + write O [b, i, h*64+d] ----
    const float inv0 = 1.0f / l0, inv1 = 1.0f / l1;
    const int row0 = i0 + w * 16 + g, row1 = row0 + 8;
#pragma unroll
    for (int dd = 0; dd < 8; dd++) {
        const int col = h * DHH + dd * 8 + 2 * t;
        *(float2*)(obuf + (size_t)(b * NT + row0) * INNER + col) =
            make_float2(o[dd][0] * inv0, o[dd][1] * inv0);
        *(float2*)(obuf + (size_t)(b * NT + row1) * INNER + col) =
            make_float2(o[dd][2] * inv1, o[dd][3] * inv1);
    }
}

// ---------------------------------------------------------------------------
extern "C" void kernel_launch(void* const* d_in, const int* in_sizes, int n_in,
                              void* d_out, int out_size)
{
    const float* x     = (const float*)d_in[0];
    const float* cd    = (const float*)d_in[1];
    const float* Wqkv  = (const float*)d_in[2];
    const float* Wout  = (const float*)d_in[3];
    const float* bout  = (const float*)d_in[4];
    const float* rel_w = (const float*)d_in[5];
    const float* rel_b = (const float*)d_in[6];
    float* out = (float*)d_out;

    float *qkvb = nullptr, *obuf = nullptr;
    cudaGetSymbolAddress((void**)&qkvb, g_qkv);
    cudaGetSymbolAddress((void**)&obuf, g_obuf);

    cudaFuncSetAttribute(attn_kernel, cudaFuncAttributeMaxDynamicSharedMemorySize,
                         ATTN_SMEM_BYTES);

    dim3 blk(256);
    // qkv = x @ Wqkv : [8192,512] x [512,1536], outputs tf32-rounded
    sgemm_kernel<false, true><<<dim3(QKVC / 64, (BB * NT) / 64), blk>>>(
        x, Wqkv, nullptr, qkvb, BB * NT, QKVC, DD);
    // fused attention (h fastest in grid.x for cd L2 reuse)
    attn_kernel<<<dim3(HH * (NT / 128), BB), blk, ATTN_SMEM_BYTES>>>(
        qkvb, cd, rel_w, rel_b, obuf);
    // out = obuf @ Wout + bout : full fp32
    sgemm_kernel<true, false><<<dim3(DD / 64, (BB * NT) / 64), blk>>>(
        obuf, Wout, bout, out, BB * NT, DD, DD);
}

// round 6
// speedup vs baseline: 1.1876x; 1.1876x over previous
#include <cuda_runtime.h>
#include <cstdint>

#define BB 4
#define NT 2048
#define DD 512
#define HH 8
#define DHH 64
#define INNER 512
#define QKVC 1536
#define ATT_SCALE 0.125f
#define NJT 32            // 2048/64 j-tiles

// Scratch (device globals — no cudaMalloc allowed)
static __device__ float g_qkv[(size_t)BB * NT * QKVC];   // tf32-rounded
static __device__ float g_obuf[(size_t)BB * NT * INNER];

// ---------------------------------------------------------------------------
// helpers
// ---------------------------------------------------------------------------
__device__ __forceinline__ uint32_t f2tf32(float x) {
    uint32_t r;
    asm("cvt.rna.tf32.f32 %0, %1;" : "=r"(r) : "f"(x));
    return r;
}

__device__ __forceinline__ uint32_t smaddr(const void* p) {
    uint32_t a;
    asm("{.reg .u64 t; cvta.to.shared.u64 t, %1; cvt.u32.u64 %0, t;}"
        : "=r"(a) : "l"(p));
    return a;
}

__device__ __forceinline__ void mma_tf32(float c[4], uint32_t a0, uint32_t a1,
                                         uint32_t a2, uint32_t a3,
                                         uint32_t b0, uint32_t b1) {
    asm volatile(
        "mma.sync.aligned.m16n8k8.row.col.f32.tf32.tf32.f32 "
        "{%0,%1,%2,%3}, {%4,%5,%6,%7}, {%8,%9}, {%0,%1,%2,%3};"
        : "+f"(c[0]), "+f"(c[1]), "+f"(c[2]), "+f"(c[3])
        : "r"(a0), "r"(a1), "r"(a2), "r"(a3), "r"(b0), "r"(b1));
}

__device__ __forceinline__ void bulk_cp(uint32_t dst, const void* src,
                                        uint32_t bytes, uint32_t mbar) {
    asm volatile(
        "cp.async.bulk.shared::cta.global.mbarrier::complete_tx::bytes "
        "[%0], [%1], %2, [%3];"
        :: "r"(dst), "l"(src), "r"(bytes), "r"(mbar) : "memory");
}

__device__ __forceinline__ void mbar_expect(uint32_t mbar, uint32_t bytes) {
    asm volatile("mbarrier.arrive.expect_tx.shared.b64 _, [%0], %1;"
                 :: "r"(mbar), "r"(bytes) : "memory");
}

__device__ __forceinline__ void mbar_wait(uint32_t mbar, uint32_t parity) {
    uint32_t done;
    do {
        asm volatile(
            "{.reg .pred p; "
            "mbarrier.try_wait.parity.acquire.cta.shared::cta.b64 p, [%1], %2, 0x989680; "
            "selp.b32 %0,1,0,p;}"
            : "=r"(done) : "r"(mbar), "r"(parity) : "memory");
    } while (!done);
}

// ---------------------------------------------------------------------------
// SGEMM (R1 proven version): 64x64 tile, K-step 16, 256 thr, 4x4 micro.
// TFR: round outputs to tf32 (rna).
// ---------------------------------------------------------------------------
template <bool HAS_BIAS, bool TFR>
__global__ __launch_bounds__(256) void sgemm_kernel(
    const float* __restrict__ A, const float* __restrict__ Bm,
    const float* __restrict__ bias, float* __restrict__ C,
    int M, int Ncols, int K)
{
    __shared__ float As[16][68];
    __shared__ float Bs[16][68];
    const int tid = threadIdx.x;
    const int tx = tid & 15, ty = tid >> 4;
    const int m0 = blockIdx.y << 6, n0 = blockIdx.x << 6;
    const int ar = tid >> 2, ac4 = (tid & 3) << 2;
    const int bkr = tid >> 4, bc = (tid & 15) << 2;

    float acc[4][4] = {};

    for (int k0 = 0; k0 < K; k0 += 16) {
        float4 a = *(const float4*)(A + (size_t)(m0 + ar) * K + (k0 + ac4));
        As[ac4 + 0][ar] = a.x;
        As[ac4 + 1][ar] = a.y;
        As[ac4 + 2][ar] = a.z;
        As[ac4 + 3][ar] = a.w;
        *(float4*)&Bs[bkr][bc] =
            *(const float4*)(Bm + (size_t)(k0 + bkr) * Ncols + (n0 + bc));
        __syncthreads();
#pragma unroll
        for (int kk = 0; kk < 16; kk++) {
            float av[4], bv[4];
            *(float4*)av = *(const float4*)&As[kk][ty << 2];
            *(float4*)bv = *(const float4*)&Bs[kk][tx << 2];
#pragma unroll
            for (int i = 0; i < 4; i++)
#pragma unroll
                for (int j = 0; j < 4; j++)
                    acc[i][j] = fmaf(av[i], bv[j], acc[i][j]);
        }
        __syncthreads();
    }

    float4 bv4 = make_float4(0.f, 0.f, 0.f, 0.f);
    if (HAS_BIAS) bv4 = *(const float4*)(bias + n0 + (tx << 2));
#pragma unroll
    for (int i = 0; i < 4; i++) {
        float4 o;
        o.x = acc[i][0] + bv4.x;
        o.y = acc[i][1] + bv4.y;
        o.z = acc[i][2] + bv4.z;
        o.w = acc[i][3] + bv4.w;
        if (TFR) {
            o.x = __uint_as_float(f2tf32(o.x));
            o.y = __uint_as_float(f2tf32(o.y));
            o.z = __uint_as_float(f2tf32(o.z));
            o.w = __uint_as_float(f2tf32(o.w));
        }
        *(float4*)(C + (size_t)(m0 + (ty << 2) + i) * Ncols + n0 + (tx << 2)) = o;
    }
}

// ---------------------------------------------------------------------------
// Fused flash attention, tf32 mma. j-tile 64, i-tile 128, 256 thr (8 warps).
// K/V double-buffered (2 mbarriers), cd single-buffered (own mbarrier, copy
// overlaps PV + next QK). P kept in registers: S-accum -> A-frag via shuffles.
// smem (floats):
//   QF  [8 wtile][8 kk][128]   Q A-fragments       32 KB   @ 0
//   KS  2 x [64][68]                               34 KB   @ 8192
//   VS  2 x [64][72]                               36 KB   @ 16896
//   CD  [3][128][68]                              102 KB   @ 26112
//   3 mbarriers after 52224 floats
// ---------------------------------------------------------------------------
#define QF0 0
#define KS_OFF 8192
#define KS_SZ 4352
#define VS_OFF 16896
#define VS_SZ 4608
#define CD_OFF 26112
#define SMF 52224
#define ATTN_SMEM_BYTES (SMF * 4 + 32)

__device__ __forceinline__ void copy_kv(int idx, int jn, int buf, int b, int h,
                                        const float* qkv, float* sm,
                                        uint32_t mbar) {
    // idx in [0,128): 0..63 K rows, 64..127 V rows. 256B each.
    mbar_expect(mbar, 256u);
    if (idx < 64) {
        const float* src = qkv + ((size_t)(b * NT + jn + idx) * QKVC
                                  + INNER + h * DHH);
        bulk_cp(smaddr(sm + KS_OFF + buf * KS_SZ + idx * 68), src, 256u, mbar);
    } else {
        const int r = idx - 64;
        const float* src = qkv + ((size_t)(b * NT + jn + r) * QKVC
                                  + 2 * INNER + h * DHH);
        bulk_cp(smaddr(sm + VS_OFF + buf * VS_SZ + r * 72), src, 256u, mbar);
    }
}

__device__ __forceinline__ void copy_cd(int idx, int jn, int b, int i0,
                                        const float* cd, float* sm,
                                        uint32_t mbar) {
    // idx in [0,384): plane p = idx>>7, local row rl = idx&127. 256B each.
    const int p = idx >> 7, rl = idx & 127;
    mbar_expect(mbar, 256u);
    const float* src = cd + ((size_t)(b * 3 + p) * NT * NT
                             + (size_t)(i0 + rl) * NT + jn);
    bulk_cp(smaddr(sm + CD_OFF + p * 8704 + rl * 68), src, 256u, mbar);
}

__global__ __launch_bounds__(256) void attn_kernel(
    const float* __restrict__ qkv, const float* __restrict__ cd,
    const float* __restrict__ rel_w, const float* __restrict__ rel_b,
    float* __restrict__ obuf)
{
    extern __shared__ float sm[];
    const int tid = threadIdx.x;
    const int lane = tid & 31, w = tid >> 5;
    const int g = lane >> 2, t = lane & 3;
    const int h = blockIdx.x & 7;            // h fastest -> cd L2 reuse
    const int i0 = (blockIdx.x >> 3) << 7;   // 128-row i tile
    const int b = blockIdx.y;

    const uint32_t mb_kv0 = smaddr(sm + SMF);
    const uint32_t mb_kv1 = mb_kv0 + 8;
    const uint32_t mb_cd  = mb_kv0 + 16;

    if (tid == 0) {
        asm volatile("mbarrier.init.shared.b64 [%0], %1;"
                     :: "r"(mb_kv0), "r"(128u) : "memory");
        asm volatile("mbarrier.init.shared.b64 [%0], %1;"
                     :: "r"(mb_kv1), "r"(128u) : "memory");
        asm volatile("mbarrier.init.shared.b64 [%0], %1;"
                     :: "r"(mb_cd), "r"(384u) : "memory");
        asm volatile("fence.proxy.async.shared::cta;" ::: "memory");
    }
    __syncthreads();

    // ---- prologue: KV tile0 -> buf0, KV tile1 -> buf1, cd tile0 ----
    if (tid < 128) {
        copy_kv(tid, 0, 0, b, h, qkv, sm, mb_kv0);
        copy_kv(tid, 64, 1, b, h, qkv, sm, mb_kv1);
    }
    copy_cd(tid, 0, b, i0, cd, sm, mb_cd);
    if (tid < 128) copy_cd(tid + 256, 0, b, i0, cd, sm, mb_cd);

    // ---- stage Q into A-fragment layout (values already tf32-rounded) ----
#pragma unroll
    for (int it = 0; it < 8; it++) {
        const int rowl = (tid >> 4) + it * 16;
        const int d4 = (tid & 15) << 2;
        float4 v = *(const float4*)(qkv + ((size_t)(b * NT + i0 + rowl) * QKVC
                                           + h * DHH + d4));
        const int wq = rowl >> 4, r16 = rowl & 15;
        const int gq = r16 & 7, hi = r16 >> 3;
        const float vv[4] = {v.x, v.y, v.z, v.w};
#pragma unroll
        for (int e = 0; e < 4; e++) {
            const int d = d4 + e;
            const int kk = d >> 3, tt = d & 3, shi = (d >> 2) & 1;
            sm[QF0 + ((wq * 8 + kk) << 7) + ((gq * 4 + tt) << 2) + hi + 2 * shi]
                = vv[e];
        }
    }
    __syncthreads();

    const float w0 = rel_w[h * 3 + 0], w1 = rel_w[h * 3 + 1], w2 = rel_w[h * 3 + 2];
    const float rb = rel_b[h];

    float m0 = -1e30f, m1 = -1e30f, l0 = 0.f, l1 = 0.f;
    float o[8][4];
#pragma unroll
    for (int dd = 0; dd < 8; dd++)
        o[dd][0] = o[dd][1] = o[dd][2] = o[dd][3] = 0.f;

    const int rl0 = w * 16 + g, rl1 = rl0 + 8;

    for (int jt = 0; jt < NJT; jt++) {
        const int buf = jt & 1;
        const float* ks = sm + KS_OFF + buf * KS_SZ;
        const float* vs = sm + VS_OFF + buf * VS_SZ;

        mbar_wait(buf ? mb_kv1 : mb_kv0, (jt >> 1) & 1);

        // ---- S = Q K^T (tf32 mma) ----
        float s_[8][4];
#pragma unroll
        for (int nn = 0; nn < 8; nn++)
            s_[nn][0] = s_[nn][1] = s_[nn][2] = s_[nn][3] = 0.f;
#pragma unroll
        for (int kk = 0; kk < 8; kk++) {
            const uint4 a = *(const uint4*)&sm[QF0 + ((w * 8 + kk) << 7) + (lane << 2)];
#pragma unroll
            for (int nn = 0; nn < 8; nn++) {
                const uint32_t b0 = __float_as_uint(ks[(nn * 8 + g) * 68 + kk * 8 + t]);
                const uint32_t b1 = __float_as_uint(ks[(nn * 8 + g) * 68 + kk * 8 + t + 4]);
                mma_tf32(s_[nn], a.x, a.y, a.z, a.w, b0, b1);
            }
        }

        mbar_wait(mb_cd, jt & 1);

        // ---- bias + online softmax -> P in registers (tf32 bits) ----
        uint32_t pu0[8], pu1[8], pu2[8], pu3[8];
        float mx0 = -1e30f, mx1 = -1e30f;
#pragma unroll
        for (int nn = 0; nn < 8; nn++) {
            const int c = nn * 8 + 2 * t;
            const float2 p00 = *(const float2*)&sm[CD_OFF + rl0 * 68 + c];
            const float2 p01 = *(const float2*)&sm[CD_OFF + 8704 + rl0 * 68 + c];
            const float2 p02 = *(const float2*)&sm[CD_OFF + 17408 + rl0 * 68 + c];
            const float2 p10 = *(const float2*)&sm[CD_OFF + rl1 * 68 + c];
            const float2 p11 = *(const float2*)&sm[CD_OFF + 8704 + rl1 * 68 + c];
            const float2 p12 = *(const float2*)&sm[CD_OFF + 17408 + rl1 * 68 + c];
            s_[nn][0] = fmaf(s_[nn][0], ATT_SCALE, w0 * p00.x + w1 * p01.x + w2 * p02.x + rb);
            s_[nn][1] = fmaf(s_[nn][1], ATT_SCALE, w0 * p00.y + w1 * p01.y + w2 * p02.y + rb);
            s_[nn][2] = fmaf(s_[nn][2], ATT_SCALE, w0 * p10.x + w1 * p11.x + w2 * p12.x + rb);
            s_[nn][3] = fmaf(s_[nn][3], ATT_SCALE, w0 * p10.y + w1 * p11.y + w2 * p12.y + rb);
            mx0 = fmaxf(mx0, fmaxf(s_[nn][0], s_[nn][1]));
            mx1 = fmaxf(mx1, fmaxf(s_[nn][2], s_[nn][3]));
        }
#pragma unroll
        for (int off = 1; off <= 2; off <<= 1) {
            mx0 = fmaxf(mx0, __shfl_xor_sync(0xffffffffu, mx0, off));
            mx1 = fmaxf(mx1, __shfl_xor_sync(0xffffffffu, mx1, off));
        }
        const float mn0 = fmaxf(m0, mx0), mn1 = fmaxf(m1, mx1);
        const float fac0 = __expf(m0 - mn0), fac1 = __expf(m1 - mn1);
        m0 = mn0; m1 = mn1;
        float rs0 = 0.f, rs1 = 0.f;
#pragma unroll
        for (int nn = 0; nn < 8; nn++) {
            const float e0 = __expf(s_[nn][0] - mn0);
            const float e1 = __expf(s_[nn][1] - mn0);
            const float e2 = __expf(s_[nn][2] - mn1);
            const float e3 = __expf(s_[nn][3] - mn1);
            rs0 += e0 + e1; rs1 += e2 + e3;
            pu0[nn] = f2tf32(e0); pu1[nn] = f2tf32(e1);
            pu2[nn] = f2tf32(e2); pu3[nn] = f2tf32(e3);
        }
#pragma unroll
        for (int off = 1; off <= 2; off <<= 1) {
            rs0 += __shfl_xor_sync(0xffffffffu, rs0, off);
            rs1 += __shfl_xor_sync(0xffffffffu, rs1, off);
        }
        l0 = l0 * fac0 + rs0;
        l1 = l1 * fac1 + rs1;
#pragma unroll
        for (int dd = 0; dd < 8; dd++) {
            o[dd][0] *= fac0; o[dd][1] *= fac0;
            o[dd][2] *= fac1; o[dd][3] *= fac1;
        }

        __syncthreads();   // all warps done with cd tile jt

        if (jt + 1 < NJT) {   // refill cd for jt+1 (overlaps PV + next QK)
            const int jn = (jt + 1) << 6;
            copy_cd(tid, jn, b, i0, cd, sm, mb_cd);
            if (tid < 128) copy_cd(tid + 256, jn, b, i0, cd, sm, mb_cd);
        }

        // ---- O += P V : convert S-accum frags -> A-frags via shuffles ----
        const int L0 = (g << 2) + (t >> 1);
        const int L1 = L0 + 2;
        const bool odd = t & 1;
#pragma unroll
        for (int jj = 0; jj < 8; jj++) {
            const uint32_t x0 = __shfl_sync(0xffffffffu, pu0[jj], L0);
            const uint32_t x1 = __shfl_sync(0xffffffffu, pu1[jj], L0);
            const uint32_t x2 = __shfl_sync(0xffffffffu, pu0[jj], L1);
            const uint32_t x3 = __shfl_sync(0xffffffffu, pu1[jj], L1);
            const uint32_t y0 = __shfl_sync(0xffffffffu, pu2[jj], L0);
            const uint32_t y1 = __shfl_sync(0xffffffffu, pu3[jj], L0);
            const uint32_t y2 = __shfl_sync(0xffffffffu, pu2[jj], L1);
            const uint32_t y3 = __shfl_sync(0xffffffffu, pu3[jj], L1);
            const uint32_t a0 = odd ? x1 : x0;
            const uint32_t a2 = odd ? x3 : x2;
            const uint32_t a1 = odd ? y1 : y0;
            const uint32_t a3 = odd ? y3 : y2;
#pragma unroll
            for (int dd = 0; dd < 8; dd++) {
                const uint32_t b0 = __float_as_uint(vs[(jj * 8 + t) * 72 + dd * 8 + g]);
                const uint32_t b1 = __float_as_uint(vs[(jj * 8 + t + 4) * 72 + dd * 8 + g]);
                mma_tf32(o[dd], a0, a1, a2, a3, b0, b1);
            }
        }

        __syncthreads();   // K/V buffer jt fully consumed

        if (jt + 2 < NJT && tid < 128) {   // refill K/V buf for jt+2
            copy_kv(tid, (jt + 2) << 6, buf, b, h, qkv, sm,
                    buf ? mb_kv1 : mb_kv0);
        }
    }

    // ---- normalize + write O [b, i, h*64+d] ----
    const float inv0 = 1.0f / l0, inv1 = 1.0f / l1;
    const int row0 = i0 + rl0, row1 = i0 + rl1;
#pragma unroll
    for (int dd = 0; dd < 8; dd++) {
        const int col = h * DHH + dd * 8 + 2 * t;
        *(float2*)(obuf + (size_t)(b * NT + row0) * INNER + col) =
            make_float2(o[dd][0] * inv0, o[dd][1] * inv0);
        *(float2*)(obuf + (size_t)(b * NT + row1) * INNER + col) =
            make_float2(o[dd][2] * inv1, o[dd][3] * inv1);
    }
}

// ---------------------------------------------------------------------------
extern "C" void kernel_launch(void* const* d_in, const int* in_sizes, int n_in,
                              void* d_out, int out_size)
{
    const float* x     = (const float*)d_in[0];
    const float* cd    = (const float*)d_in[1];
    const float* Wqkv  = (const float*)d_in[2];
    const float* Wout  = (const float*)d_in[3];
    const float* bout  = (const float*)d_in[4];
    const float* rel_w = (const float*)d_in[5];
    const float* rel_b = (const float*)d_in[6];
    float* out = (float*)d_out;

    float *qkvb = nullptr, *obuf = nullptr;
    cudaGetSymbolAddress((void**)&qkvb, g_qkv);
    cudaGetSymbolAddress((void**)&obuf, g_obuf);

    cudaFuncSetAttribute(attn_kernel, cudaFuncAttributeMaxDynamicSharedMemorySize,
                         ATTN_SMEM_BYTES);

    dim3 blk(256);
    // qkv = x @ Wqkv : [8192,512] x [512,1536], outputs tf32-rounded
    sgemm_kernel<false, true><<<dim3(QKVC / 64, (BB * NT) / 64), blk>>>(
        x, Wqkv, nullptr, qkvb, BB * NT, QKVC, DD);
    // fused attention (h fastest in grid.x for cd L2 reuse)
    attn_kernel<<<dim3(HH * (NT / 128), BB), blk, ATTN_SMEM_BYTES>>>(
        qkvb, cd, rel_w, rel_b, obuf);
    // out = obuf @ Wout + bout : full fp32
    sgemm_kernel<true, false><<<dim3(DD / 64, (BB * NT) / 64), blk>>>(
        obuf, Wout, bout, out, BB * NT, DD, DD);
}

// round 7
// speedup vs baseline: 1.4038x; 1.1820x over previous
#include <cuda_runtime.h>
#include <cuda_fp16.h>
#include <cstdint>

#define BB 4
#define NT 2048
#define DD 512
#define HH 8
#define DHH 64
#define INNER 512
#define QKVC 1536
#define ATT_SCALE 0.125f
#define NJT 32            // 2048/64 j-tiles

// Scratch (device globals — no cudaMalloc allowed)
static __device__ float  g_qkv[(size_t)BB * NT * QKVC];    // fp32 GEMM out
static __device__ __half g_q16[(size_t)BB * NT * INNER];   // [b,n,h*64]
static __device__ __half g_k16[(size_t)BB * NT * INNER];   // [b,n,h*64]
static __device__ __half g_v16t[(size_t)BB * HH * DHH * NT]; // [b,h,d,n]
static __device__ float  g_obuf[(size_t)BB * NT * INNER];

// ---------------------------------------------------------------------------
// helpers
// ---------------------------------------------------------------------------
__device__ __forceinline__ uint32_t smaddr(const void* p) {
    uint32_t a;
    asm("{.reg .u64 t; cvta.to.shared.u64 t, %1; cvt.u32.u64 %0, t;}"
        : "=r"(a) : "l"(p));
    return a;
}

__device__ __forceinline__ uint32_t pack2h(float lo, float hi) {
    uint32_t d;
    asm("cvt.rn.f16x2.f32 %0, %1, %2;" : "=r"(d) : "f"(hi), "f"(lo));
    return d;
}

__device__ __forceinline__ void mma_f16(float c[4], uint32_t a0, uint32_t a1,
                                        uint32_t a2, uint32_t a3,
                                        uint32_t b0, uint32_t b1) {
    asm volatile(
        "mma.sync.aligned.m16n8k16.row.col.f32.f16.f16.f32 "
        "{%0,%1,%2,%3}, {%4,%5,%6,%7}, {%8,%9}, {%0,%1,%2,%3};"
        : "+f"(c[0]), "+f"(c[1]), "+f"(c[2]), "+f"(c[3])
        : "r"(a0), "r"(a1), "r"(a2), "r"(a3), "r"(b0), "r"(b1));
}

__device__ __forceinline__ void bulk_cp(uint32_t dst, const void* src,
                                        uint32_t bytes, uint32_t mbar) {
    asm volatile(
        "cp.async.bulk.shared::cta.global.mbarrier::complete_tx::bytes "
        "[%0], [%1], %2, [%3];"
        :: "r"(dst), "l"(src), "r"(bytes), "r"(mbar) : "memory");
}

__device__ __forceinline__ void mbar_expect(uint32_t mbar, uint32_t bytes) {
    asm volatile("mbarrier.arrive.expect_tx.shared.b64 _, [%0], %1;"
                 :: "r"(mbar), "r"(bytes) : "memory");
}

__device__ __forceinline__ void mbar_wait(uint32_t mbar, uint32_t parity) {
    uint32_t done;
    do {
        asm volatile(
            "{.reg .pred p; "
            "mbarrier.try_wait.parity.acquire.cta.shared::cta.b64 p, [%1], %2, 0x989680; "
            "selp.b32 %0,1,0,p;}"
            : "=r"(done) : "r"(mbar), "r"(parity) : "memory");
    } while (!done);
}

// ---------------------------------------------------------------------------
// SGEMM (R1 proven version): 64x64 tile, K-step 16, 256 thr, 4x4 micro.
// ---------------------------------------------------------------------------
template <bool HAS_BIAS>
__global__ __launch_bounds__(256) void sgemm_kernel(
    const float* __restrict__ A, const float* __restrict__ Bm,
    const float* __restrict__ bias, float* __restrict__ C,
    int M, int Ncols, int K)
{
    __shared__ float As[16][68];
    __shared__ float Bs[16][68];
    const int tid = threadIdx.x;
    const int tx = tid & 15, ty = tid >> 4;
    const int m0 = blockIdx.y << 6, n0 = blockIdx.x << 6;
    const int ar = tid >> 2, ac4 = (tid & 3) << 2;
    const int bkr = tid >> 4, bc = (tid & 15) << 2;

    float acc[4][4] = {};

    for (int k0 = 0; k0 < K; k0 += 16) {
        float4 a = *(const float4*)(A + (size_t)(m0 + ar) * K + (k0 + ac4));
        As[ac4 + 0][ar] = a.x;
        As[ac4 + 1][ar] = a.y;
        As[ac4 + 2][ar] = a.z;
        As[ac4 + 3][ar] = a.w;
        *(float4*)&Bs[bkr][bc] =
            *(const float4*)(Bm + (size_t)(k0 + bkr) * Ncols + (n0 + bc));
        __syncthreads();
#pragma unroll
        for (int kk = 0; kk < 16; kk++) {
            float av[4], bv[4];
            *(float4*)av = *(const float4*)&As[kk][ty << 2];
            *(float4*)bv = *(const float4*)&Bs[kk][tx << 2];
#pragma unroll
            for (int i = 0; i < 4; i++)
#pragma unroll
                for (int j = 0; j < 4; j++)
                    acc[i][j] = fmaf(av[i], bv[j], acc[i][j]);
        }
        __syncthreads();
    }

    float4 bv4 = make_float4(0.f, 0.f, 0.f, 0.f);
    if (HAS_BIAS) bv4 = *(const float4*)(bias + n0 + (tx << 2));
#pragma unroll
    for (int i = 0; i < 4; i++) {
        float4 o;
        o.x = acc[i][0] + bv4.x;
        o.y = acc[i][1] + bv4.y;
        o.z = acc[i][2] + bv4.z;
        o.w = acc[i][3] + bv4.w;
        *(float4*)(C + (size_t)(m0 + (ty << 2) + i) * Ncols + n0 + (tx << 2)) = o;
    }
}

// ---------------------------------------------------------------------------
// Pack: qkv fp32 -> q16/k16 [b,n,h*64] halves, v -> v16t [b,h,d,n] halves.
// One block per (b, h, 64-token tile). 256 threads.
// ---------------------------------------------------------------------------
__global__ __launch_bounds__(256) void pack_kernel(
    const float* __restrict__ qkv, __half* __restrict__ q16,
    __half* __restrict__ k16, __half* __restrict__ v16t)
{
    __shared__ __half vs[64 * 72];
    const int tid = threadIdx.x;
    const int h = blockIdx.x & 7;
    const int n0 = (blockIdx.x >> 3) << 6;
    const int b = blockIdx.y;

#pragma unroll
    for (int it = 0; it < 8; it++) {
        const int idx = tid + (it << 8);          // 0..2047
        const int row = idx >> 5;                 // 0..63 token-local
        const int col = (idx & 31) << 1;          // even col 0..62
        const float* src = qkv + (size_t)(b * NT + n0 + row) * QKVC + h * DHH + col;
        const float2 vq = *(const float2*)(src);
        const float2 vk = *(const float2*)(src + INNER);
        const float2 vv = *(const float2*)(src + 2 * INNER);
        const size_t dsto = (size_t)(b * NT + n0 + row) * INNER + h * DHH + col;
        *(__half2*)(q16 + dsto) = __float22half2_rn(vq);
        *(__half2*)(k16 + dsto) = __float22half2_rn(vk);
        vs[col * 72 + row] = __float2half_rn(vv.x);
        vs[(col + 1) * 72 + row] = __float2half_rn(vv.y);
    }
    __syncthreads();
#pragma unroll
    for (int it = 0; it < 8; it++) {
        const int idx = tid + (it << 8);
        const int d = idx >> 5;
        const int j = (idx & 31) << 1;
        *(uint32_t*)(v16t + ((size_t)((b * HH + h) * DHH + d)) * NT + n0 + j) =
            *(const uint32_t*)&vs[d * 72 + j];
    }
}

// ---------------------------------------------------------------------------
// Fused flash attention, fp16 mma m16n8k16. j-tile 64, i-tile 128, 8 warps.
// Q A-frags in registers. P: accum->A-frag by register cvt (no shuffles).
// K/V fp16 double-buffered via bulk-async; cd fp32 single-buffered.
// smem (bytes):
//   KS  2 x [64 rows][72 halves]   18432 @ 0
//   VT  2 x [64 rows][72 halves]   18432 @ 18432
//   CD  [3][128][68] fp32         104448 @ 36864
//   3 mbarriers                          @ 141312
// ---------------------------------------------------------------------------
#define KS_B 0
#define KS_SZB 9216
#define VT_B 18432
#define VT_SZB 9216
#define CD_B 36864
#define MB_B 141312
#define ATTN_SMEM_BYTES 141344

__device__ __forceinline__ void copy_kv(int idx, int jn, int buf, int b, int h,
                                        const __half* k16, const __half* v16t,
                                        char* smc, uint32_t mbar) {
    // idx in [0,128): 0..63 K rows, 64..127 V d-rows. 128B each.
    mbar_expect(mbar, 128u);
    if (idx < 64) {
        const __half* src = k16 + (size_t)(b * NT + jn + idx) * INNER + h * DHH;
        bulk_cp(smaddr(smc + KS_B + buf * KS_SZB + idx * 144), src, 128u, mbar);
    } else {
        const int r = idx - 64;
        const __half* src = v16t + ((size_t)((b * HH + h) * DHH + r)) * NT + jn;
        bulk_cp(smaddr(smc + VT_B + buf * VT_SZB + r * 144), src, 128u, mbar);
    }
}

__device__ __forceinline__ void copy_cd(int idx, int jn, int b, int i0,
                                        const float* cd, char* smc,
                                        uint32_t mbar) {
    const int p = idx >> 7, rl = idx & 127;
    mbar_expect(mbar, 256u);
    const float* src = cd + ((size_t)(b * 3 + p) * NT * NT
                             + (size_t)(i0 + rl) * NT + jn);
    bulk_cp(smaddr(smc + CD_B + (p * 8704 + rl * 68) * 4), src, 256u, mbar);
}

__global__ __launch_bounds__(256) void attn_kernel(
    const __half* __restrict__ q16, const __half* __restrict__ k16,
    const __half* __restrict__ v16t, const float* __restrict__ cd,
    const float* __restrict__ rel_w, const float* __restrict__ rel_b,
    float* __restrict__ obuf)
{
    extern __shared__ char smc[];
    const int tid = threadIdx.x;
    const int lane = tid & 31, w = tid >> 5;
    const int g = lane >> 2, t = lane & 3;
    const int h = blockIdx.x & 7;            // h fastest -> cd L2 reuse
    const int i0 = (blockIdx.x >> 3) << 7;   // 128-row i tile
    const int b = blockIdx.y;

    const uint32_t mb_kv0 = smaddr(smc + MB_B);
    const uint32_t mb_kv1 = mb_kv0 + 8;
    const uint32_t mb_cd  = mb_kv0 + 16;

    if (tid == 0) {
        asm volatile("mbarrier.init.shared.b64 [%0], %1;"
                     :: "r"(mb_kv0), "r"(128u) : "memory");
        asm volatile("mbarrier.init.shared.b64 [%0], %1;"
                     :: "r"(mb_kv1), "r"(128u) : "memory");
        asm volatile("mbarrier.init.shared.b64 [%0], %1;"
                     :: "r"(mb_cd), "r"(384u) : "memory");
        asm volatile("fence.proxy.async.shared::cta;" ::: "memory");
    }
    __syncthreads();

    // ---- prologue: KV tile0 -> buf0, KV tile1 -> buf1, cd tile0 ----
    if (tid < 128) {
        copy_kv(tid, 0, 0, b, h, k16, v16t, smc, mb_kv0);
        copy_kv(tid, 64, 1, b, h, k16, v16t, smc, mb_kv1);
    }
    copy_cd(tid, 0, b, i0, cd, smc, mb_cd);
    if (tid < 128) copy_cd(tid + 256, 0, b, i0, cd, smc, mb_cd);

    // ---- Q A-fragments into registers (16 x LDG.32, once per block) ----
    uint32_t qa[4][4];
#pragma unroll
    for (int kk = 0; kk < 4; kk++)
#pragma unroll
        for (int r = 0; r < 4; r++) {
            const int row = i0 + w * 16 + g + ((r & 1) ? 8 : 0);
            const int col = h * DHH + kk * 16 + 2 * t + ((r & 2) ? 8 : 0);
            qa[kk][r] = *(const uint32_t*)(q16 + (size_t)(b * NT + row) * INNER + col);
        }

    const float w0 = rel_w[h * 3 + 0], w1 = rel_w[h * 3 + 1], w2 = rel_w[h * 3 + 2];
    const float rb = rel_b[h];
    const float* cdf = (const float*)(smc + CD_B);

    float m0 = -1e30f, m1 = -1e30f, l0 = 0.f, l1 = 0.f;
    float o[8][4];
#pragma unroll
    for (int dd = 0; dd < 8; dd++)
        o[dd][0] = o[dd][1] = o[dd][2] = o[dd][3] = 0.f;

    const int rl0 = w * 16 + g, rl1 = rl0 + 8;

    for (int jt = 0; jt < NJT; jt++) {
        const int buf = jt & 1;
        const uint32_t* ksw = (const uint32_t*)(smc + KS_B + buf * KS_SZB);
        const uint32_t* vtw = (const uint32_t*)(smc + VT_B + buf * VT_SZB);

        mbar_wait(buf ? mb_kv1 : mb_kv0, (jt >> 1) & 1);

        // ---- S = Q K^T (fp16 mma, fp32 accum) ----
        float s_[8][4];
#pragma unroll
        for (int nn = 0; nn < 8; nn++)
            s_[nn][0] = s_[nn][1] = s_[nn][2] = s_[nn][3] = 0.f;
#pragma unroll
        for (int kk = 0; kk < 4; kk++) {
#pragma unroll
            for (int nn = 0; nn < 8; nn++) {
                const uint32_t b0 = ksw[(nn * 8 + g) * 36 + kk * 8 + t];
                const uint32_t b1 = ksw[(nn * 8 + g) * 36 + kk * 8 + t + 4];
                mma_f16(s_[nn], qa[kk][0], qa[kk][1], qa[kk][2], qa[kk][3], b0, b1);
            }
        }

        mbar_wait(mb_cd, jt & 1);

        // ---- bias + online softmax (exps kept in fp32 regs) ----
        float mx0 = -1e30f, mx1 = -1e30f;
#pragma unroll
        for (int nn = 0; nn < 8; nn++) {
            const int c = nn * 8 + 2 * t;
            const float2 p00 = *(const float2*)&cdf[rl0 * 68 + c];
            const float2 p01 = *(const float2*)&cdf[8704 + rl0 * 68 + c];
            const float2 p02 = *(const float2*)&cdf[17408 + rl0 * 68 + c];
            const float2 p10 = *(const float2*)&cdf[rl1 * 68 + c];
            const float2 p11 = *(const float2*)&cdf[8704 + rl1 * 68 + c];
            const float2 p12 = *(const float2*)&cdf[17408 + rl1 * 68 + c];
            s_[nn][0] = fmaf(s_[nn][0], ATT_SCALE, w0 * p00.x + w1 * p01.x + w2 * p02.x + rb);
            s_[nn][1] = fmaf(s_[nn][1], ATT_SCALE, w0 * p00.y + w1 * p01.y + w2 * p02.y + rb);
            s_[nn][2] = fmaf(s_[nn][2], ATT_SCALE, w0 * p10.x + w1 * p11.x + w2 * p12.x + rb);
            s_[nn][3] = fmaf(s_[nn][3], ATT_SCALE, w0 * p10.y + w1 * p11.y + w2 * p12.y + rb);
            mx0 = fmaxf(mx0, fmaxf(s_[nn][0], s_[nn][1]));
            mx1 = fmaxf(mx1, fmaxf(s_[nn][2], s_[nn][3]));
        }
#pragma unroll
        for (int off = 1; off <= 2; off <<= 1) {
            mx0 = fmaxf(mx0, __shfl_xor_sync(0xffffffffu, mx0, off));
            mx1 = fmaxf(mx1, __shfl_xor_sync(0xffffffffu, mx1, off));
        }
        const float mn0 = fmaxf(m0, mx0), mn1 = fmaxf(m1, mx1);
        const float fac0 = __expf(m0 - mn0), fac1 = __expf(m1 - mn1);
        m0 = mn0; m1 = mn1;
        float rs0 = 0.f, rs1 = 0.f;
#pragma unroll
        for (int nn = 0; nn < 8; nn++) {
            s_[nn][0] = __expf(s_[nn][0] - mn0);
            s_[nn][1] = __expf(s_[nn][1] - mn0);
            s_[nn][2] = __expf(s_[nn][2] - mn1);
            s_[nn][3] = __expf(s_[nn][3] - mn1);
            rs0 += s_[nn][0] + s_[nn][1];
            rs1 += s_[nn][2] + s_[nn][3];
        }
#pragma unroll
        for (int off = 1; off <= 2; off <<= 1) {
            rs0 += __shfl_xor_sync(0xffffffffu, rs0, off);
            rs1 += __shfl_xor_sync(0xffffffffu, rs1, off);
        }
        l0 = l0 * fac0 + rs0;
        l1 = l1 * fac1 + rs1;
#pragma unroll
        for (int dd = 0; dd < 8; dd++) {
            o[dd][0] *= fac0; o[dd][1] *= fac0;
            o[dd][2] *= fac1; o[dd][3] *= fac1;
        }

        __syncthreads();   // all warps done with cd tile jt

        if (jt + 1 < NJT) {   // refill cd for jt+1 (overlaps PV + next QK)
            const int jn = (jt + 1) << 6;
            copy_cd(tid, jn, b, i0, cd, smc, mb_cd);
            if (tid < 128) copy_cd(tid + 256, jn, b, i0, cd, smc, mb_cd);
        }

        // ---- O += P V : accum frag == A frag layout, register cvt only ----
#pragma unroll
        for (int jj = 0; jj < 4; jj++) {
            const uint32_t a0 = pack2h(s_[2 * jj][0], s_[2 * jj][1]);
            const uint32_t a1 = pack2h(s_[2 * jj][2], s_[2 * jj][3]);
            const uint32_t a2 = pack2h(s_[2 * jj + 1][0], s_[2 * jj + 1][1]);
            const uint32_t a3 = pack2h(s_[2 * jj + 1][2], s_[2 * jj + 1][3]);
#pragma unroll
            for (int dd = 0; dd < 8; dd++) {
                const uint32_t b0 = vtw[(dd * 8 + g) * 36 + jj * 8 + t];
                const uint32_t b1 = vtw[(dd * 8 + g) * 36 + jj * 8 + t + 4];
                mma_f16(o[dd], a0, a1, a2, a3, b0, b1);
            }
        }

        __syncthreads();   // K/V buffer jt fully consumed

        if (jt + 2 < NJT && tid < 128) {   // refill K/V buf for jt+2
            copy_kv(tid, (jt + 2) << 6, buf, b, h, k16, v16t, smc,
                    buf ? mb_kv1 : mb_kv0);
        }
    }

    // ---- normalize + write O [b, i, h*64+d] ----
    const float inv0 = 1.0f / l0, inv1 = 1.0f / l1;
    const int row0 = i0 + rl0, row1 = i0 + rl1;
#pragma unroll
    for (int dd = 0; dd < 8; dd++) {
        const int col = h * DHH + dd * 8 + 2 * t;
        *(float2*)(obuf + (size_t)(b * NT + row0) * INNER + col) =
            make_float2(o[dd][0] * inv0, o[dd][1] * inv0);
        *(float2*)(obuf + (size_t)(b * NT + row1) * INNER + col) =
            make_float2(o[dd][2] * inv1, o[dd][3] * inv1);
    }
}

// ---------------------------------------------------------------------------
extern "C" void kernel_launch(void* const* d_in, const int* in_sizes, int n_in,
                              void* d_out, int out_size)
{
    const float* x     = (const float*)d_in[0];
    const float* cd    = (const float*)d_in[1];
    const float* Wqkv  = (const float*)d_in[2];
    const float* Wout  = (const float*)d_in[3];
    const float* bout  = (const float*)d_in[4];
    const float* rel_w = (const float*)d_in[5];
    const float* rel_b = (const float*)d_in[6];
    float* out = (float*)d_out;

    float *qkvb = nullptr, *obuf = nullptr;
    __half *q16 = nullptr, *k16 = nullptr, *v16t = nullptr;
    cudaGetSymbolAddress((void**)&qkvb, g_qkv);
    cudaGetSymbolAddress((void**)&obuf, g_obuf);
    cudaGetSymbolAddress((void**)&q16, g_q16);
    cudaGetSymbolAddress((void**)&k16, g_k16);
    cudaGetSymbolAddress((void**)&v16t, g_v16t);

    cudaFuncSetAttribute(attn_kernel, cudaFuncAttributeMaxDynamicSharedMemorySize,
                         ATTN_SMEM_BYTES);

    dim3 blk(256);
    // qkv = x @ Wqkv : [8192,512] x [512,1536]
    sgemm_kernel<false><<<dim3(QKVC / 64, (BB * NT) / 64), blk>>>(
        x, Wqkv, nullptr, qkvb, BB * NT, QKVC, DD);
    // pack to fp16 (q,k row-major; v transposed per head)
    pack_kernel<<<dim3(HH * (NT / 64), BB), blk>>>(qkvb, q16, k16, v16t);
    // fused attention (h fastest in grid.x for cd L2 reuse)
    attn_kernel<<<dim3(HH * (NT / 128), BB), blk, ATTN_SMEM_BYTES>>>(
        q16, k16, v16t, cd, rel_w, rel_b, obuf);
    // out = obuf @ Wout + bout : full fp32
    sgemm_kernel<true><<<dim3(DD / 64, (BB * NT) / 64), blk>>>(
        obuf, Wout, bout, out, BB * NT, DD, DD);
}

// round 9
// speedup vs baseline: 1.7451x; 1.2431x over previous
#include <cuda_runtime.h>
#include <cuda_fp16.h>
#include <cstdint>

#define BB 4
#define NT 2048
#define DD 512
#define HH 8
#define DHH 64
#define INNER 512
#define QKVC 1536
#define ATT_SCALE 0.125f
#define NJT 32            // 2048/64 j-tiles

// Scratch (device globals — no cudaMalloc allowed)
static __device__ float  g_qkv[(size_t)BB * NT * QKVC];      // fp32 GEMM out
static __device__ __half g_q16[(size_t)BB * NT * INNER];     // [b,n,h*64]
static __device__ __half g_k16[(size_t)BB * NT * INNER];     // [b,n,h*64]
static __device__ __half g_v16t[(size_t)BB * HH * DHH * NT]; // [b,h,d,n]
static __device__ float  g_bias32[(size_t)BB * HH * NT * NT];// [b,h,i,j] 537MB
static __device__ float  g_obuf[(size_t)BB * NT * INNER];

// ---------------------------------------------------------------------------
// helpers
// ---------------------------------------------------------------------------
__device__ __forceinline__ uint32_t smaddr(const void* p) {
    uint32_t a;
    asm("{.reg .u64 t; cvta.to.shared.u64 t, %1; cvt.u32.u64 %0, t;}"
        : "=r"(a) : "l"(p));
    return a;
}

__device__ __forceinline__ uint32_t pack2h(float lo, float hi) {
    uint32_t d;
    asm("cvt.rn.f16x2.f32 %0, %1, %2;" : "=r"(d) : "f"(hi), "f"(lo));
    return d;
}

__device__ __forceinline__ void mma_f16(float c[4], uint32_t a0, uint32_t a1,
                                        uint32_t a2, uint32_t a3,
                                        uint32_t b0, uint32_t b1) {
    asm volatile(
        "mma.sync.aligned.m16n8k16.row.col.f32.f16.f16.f32 "
        "{%0,%1,%2,%3}, {%4,%5,%6,%7}, {%8,%9}, {%0,%1,%2,%3};"
        : "+f"(c[0]), "+f"(c[1]), "+f"(c[2]), "+f"(c[3])
        : "r"(a0), "r"(a1), "r"(a2), "r"(a3), "r"(b0), "r"(b1));
}

__device__ __forceinline__ void bulk_cp(uint32_t dst, const void* src,
                                        uint32_t bytes, uint32_t mbar) {
    asm volatile(
        "cp.async.bulk.shared::cta.global.mbarrier::complete_tx::bytes "
        "[%0], [%1], %2, [%3];"
        :: "r"(dst), "l"(src), "r"(bytes), "r"(mbar) : "memory");
}

__device__ __forceinline__ void mbar_expect(uint32_t mbar, uint32_t bytes) {
    asm volatile("mbarrier.arrive.expect_tx.shared.b64 _, [%0], %1;"
                 :: "r"(mbar), "r"(bytes) : "memory");
}

__device__ __forceinline__ void mbar_wait(uint32_t mbar, uint32_t parity) {
    uint32_t done;
    do {
        asm volatile(
            "{.reg .pred p; "
            "mbarrier.try_wait.parity.acquire.cta.shared::cta.b64 p, [%1], %2, 0x989680; "
            "selp.b32 %0,1,0,p;}"
            : "=r"(done) : "r"(mbar), "r"(parity) : "memory");
    } while (!done);
}

// ---------------------------------------------------------------------------
// SGEMM fp32 (proven): 64x64 tile, K-step 16, 256 thr, 4x4 micro.
// ---------------------------------------------------------------------------
template <bool HAS_BIAS>
__global__ __launch_bounds__(256) void sgemm_kernel(
    const float* __restrict__ A, const float* __restrict__ Bm,
    const float* __restrict__ bias, float* __restrict__ C,
    int M, int Ncols, int K)
{
    __shared__ float As[16][68];
    __shared__ float Bs[16][68];
    const int tid = threadIdx.x;
    const int tx = tid & 15, ty = tid >> 4;
    const int m0 = blockIdx.y << 6, n0 = blockIdx.x << 6;
    const int ar = tid >> 2, ac4 = (tid & 3) << 2;
    const int bkr = tid >> 4, bc = (tid & 15) << 2;

    float acc[4][4] = {};

    for (int k0 = 0; k0 < K; k0 += 16) {
        float4 a = *(const float4*)(A + (size_t)(m0 + ar) * K + (k0 + ac4));
        As[ac4 + 0][ar] = a.x;
        As[ac4 + 1][ar] = a.y;
        As[ac4 + 2][ar] = a.z;
        As[ac4 + 3][ar] = a.w;
        *(float4*)&Bs[bkr][bc] =
            *(const float4*)(Bm + (size_t)(k0 + bkr) * Ncols + (n0 + bc));
        __syncthreads();
#pragma unroll
        for (int kk = 0; kk < 16; kk++) {
            float av[4], bv[4];
            *(float4*)av = *(const float4*)&As[kk][ty << 2];
            *(float4*)bv = *(const float4*)&Bs[kk][tx << 2];
#pragma unroll
            for (int i = 0; i < 4; i++)
#pragma unroll
                for (int j = 0; j < 4; j++)
                    acc[i][j] = fmaf(av[i], bv[j], acc[i][j]);
        }
        __syncthreads();
    }

    float4 bv4 = make_float4(0.f, 0.f, 0.f, 0.f);
    if (HAS_BIAS) bv4 = *(const float4*)(bias + n0 + (tx << 2));
#pragma unroll
    for (int i = 0; i < 4; i++) {
        float4 o;
        o.x = acc[i][0] + bv4.x;
        o.y = acc[i][1] + bv4.y;
        o.z = acc[i][2] + bv4.z;
        o.w = acc[i][3] + bv4.w;
        *(float4*)(C + (size_t)(m0 + (ty << 2) + i) * Ncols + n0 + (tx << 2)) = o;
    }
}

// ---------------------------------------------------------------------------
// Pack: qkv fp32 -> q16/k16 [b,n,h*64], v -> v16t [b,h,d,n] (proven R6)
// ---------------------------------------------------------------------------
__global__ __launch_bounds__(256) void pack_kernel(
    const float* __restrict__ qkv, __half* __restrict__ q16,
    __half* __restrict__ k16, __half* __restrict__ v16t)
{
    __shared__ __half vs[64 * 72];
    const int tid = threadIdx.x;
    const int h = blockIdx.x & 7;
    const int n0 = (blockIdx.x >> 3) << 6;
    const int b = blockIdx.y;

#pragma unroll
    for (int it = 0; it < 8; it++) {
        const int idx = tid + (it << 8);
        const int row = idx >> 5;
        const int col = (idx & 31) << 1;
        const float* src = qkv + (size_t)(b * NT + n0 + row) * QKVC + h * DHH + col;
        const float2 vq = *(const float2*)(src);
        const float2 vk = *(const float2*)(src + INNER);
        const float2 vv = *(const float2*)(src + 2 * INNER);
        const size_t dsto = (size_t)(b * NT + n0 + row) * INNER + h * DHH + col;
        *(__half2*)(q16 + dsto) = __float22half2_rn(vq);
        *(__half2*)(k16 + dsto) = __float22half2_rn(vk);
        vs[col * 72 + row] = __float2half_rn(vv.x);
        vs[(col + 1) * 72 + row] = __float2half_rn(vv.y);
    }
    __syncthreads();
#pragma unroll
    for (int it = 0; it < 8; it++) {
        const int idx = tid + (it << 8);
        const int d = idx >> 5;
        const int j = (idx & 31) << 1;
        *(uint32_t*)(v16t + ((size_t)((b * HH + h) * DHH + d)) * NT + n0 + j) =
            *(const uint32_t*)&vs[d * 72 + j];
    }
}

// ---------------------------------------------------------------------------
// bias32[b,h,i,j] = sum_c rel_w[h,c]*cd[b,c,i,j] + rel_b[h]   (fp32)
// ---------------------------------------------------------------------------
__global__ __launch_bounds__(256) void bias_kernel(
    const float* __restrict__ cd, const float* __restrict__ rel_w,
    const float* __restrict__ rel_b, float* __restrict__ bias32)
{
    const int b = blockIdx.y;
    const size_t pos = (size_t)blockIdx.x * 256 + threadIdx.x; // i*512 + j4
    const int i = (int)(pos >> 9);
    const int j = (int)(pos & 511) << 2;
    const size_t NN2 = (size_t)NT * NT;
    const size_t ro = (size_t)i * NT + j;
    const float4 c0 = *(const float4*)(cd + (size_t)b * 3 * NN2 + ro);
    const float4 c1 = *(const float4*)(cd + ((size_t)b * 3 + 1) * NN2 + ro);
    const float4 c2 = *(const float4*)(cd + ((size_t)b * 3 + 2) * NN2 + ro);
#pragma unroll
    for (int h = 0; h < HH; h++) {
        const float w0 = __ldg(rel_w + h * 3 + 0);
        const float w1 = __ldg(rel_w + h * 3 + 1);
        const float w2 = __ldg(rel_w + h * 3 + 2);
        const float rb = __ldg(rel_b + h);
        float4 o;
        o.x = w0 * c0.x + w1 * c1.x + w2 * c2.x + rb;
        o.y = w0 * c0.y + w1 * c1.y + w2 * c2.y + rb;
        o.z = w0 * c0.z + w1 * c1.z + w2 * c2.z + rb;
        o.w = w0 * c0.w + w1 * c1.w + w2 * c2.w + rb;
        *(float4*)(bias32 + ((size_t)(b * HH + h) * NT + i) * NT + j) = o;
    }
}

// ---------------------------------------------------------------------------
// Fused flash attention, fp16 mma. j-tile 64, i-tile 128, 8 warps, 2 CTA/SM.
// K/V (fp16) + bias (fp32) all double-buffered via bulk-async.
// smem (bytes): KS 2x9216 @0, VT 2x9216 @18432, BS 2x34816 @36864, mbar @106496
// ---------------------------------------------------------------------------
#define KS_B 0
#define KS_SZB 9216
#define VT_B 18432
#define VT_SZB 9216
#define BS_B 36864
#define BS_SZB 34816
#define MB_B 106496
#define ATTN_SMEM_BYTES 106528

__device__ __forceinline__ void copy_kv(int idx, int jn, int buf, int b, int h,
                                        const __half* k16, const __half* v16t,
                                        char* smc, uint32_t mbar) {
    mbar_expect(mbar, 128u);
    if (idx < 64) {
        const __half* src = k16 + (size_t)(b * NT + jn + idx) * INNER + h * DHH;
        bulk_cp(smaddr(smc + KS_B + buf * KS_SZB + idx * 144), src, 128u, mbar);
    } else {
        const int r = idx - 64;
        const __half* src = v16t + ((size_t)((b * HH + h) * DHH + r)) * NT + jn;
        bulk_cp(smaddr(smc + VT_B + buf * VT_SZB + r * 144), src, 128u, mbar);
    }
}

__device__ __forceinline__ void copy_bs(int idx, int jn, int buf, int b, int h,
                                        int i0, const float* bias32,
                                        char* smc, uint32_t mbar) {
    mbar_expect(mbar, 256u);
    const float* src = bias32 + ((size_t)(b * HH + h) * NT + i0 + idx) * NT + jn;
    bulk_cp(smaddr(smc + BS_B + buf * BS_SZB + idx * 272), src, 256u, mbar);
}

__global__ __launch_bounds__(256, 2) void attn_kernel(
    const __half* __restrict__ q16, const __half* __restrict__ k16,
    const __half* __restrict__ v16t, const float* __restrict__ bias32,
    float* __restrict__ obuf)
{
    extern __shared__ char smc[];
    const int tid = threadIdx.x;
    const int lane = tid & 31, w = tid >> 5;
    const int g = lane >> 2, t = lane & 3;
    const int h = blockIdx.x & 7;
    const int i0 = (blockIdx.x >> 3) << 7;
    const int b = blockIdx.y;

    const uint32_t mb_kv0 = smaddr(smc + MB_B);
    const uint32_t mb_kv1 = mb_kv0 + 8;
    const uint32_t mb_bs0 = mb_kv0 + 16;
    const uint32_t mb_bs1 = mb_kv0 + 24;

    if (tid == 0) {
        asm volatile("mbarrier.init.shared.b64 [%0], %1;" :: "r"(mb_kv0), "r"(128u) : "memory");
        asm volatile("mbarrier.init.shared.b64 [%0], %1;" :: "r"(mb_kv1), "r"(128u) : "memory");
        asm volatile("mbarrier.init.shared.b64 [%0], %1;" :: "r"(mb_bs0), "r"(128u) : "memory");
        asm volatile("mbarrier.init.shared.b64 [%0], %1;" :: "r"(mb_bs1), "r"(128u) : "memory");
        asm volatile("fence.proxy.async.shared::cta;" ::: "memory");
    }
    __syncthreads();

    // ---- prologue: tiles 0 and 1 into bufs 0 and 1 ----
    if (tid < 128) {
        copy_kv(tid, 0, 0, b, h, k16, v16t, smc, mb_kv0);
        copy_kv(tid, 64, 1, b, h, k16, v16t, smc, mb_kv1);
    } else {
        copy_bs(tid - 128, 0, 0, b, h, i0, bias32, smc, mb_bs0);
        copy_bs(tid - 128, 64, 1, b, h, i0, bias32, smc, mb_bs1);
    }

    // ---- Q A-fragments into registers (16 x LDG.32) ----
    uint32_t qa[4][4];
#pragma unroll
    for (int kk = 0; kk < 4; kk++)
#pragma unroll
        for (int r = 0; r < 4; r++) {
            const int row = i0 + w * 16 + g + ((r & 1) ? 8 : 0);
            const int col = h * DHH + kk * 16 + 2 * t + ((r & 2) ? 8 : 0);
            qa[kk][r] = *(const uint32_t*)(q16 + (size_t)(b * NT + row) * INNER + col);
        }

    float m0 = -1e30f, m1 = -1e30f, l0 = 0.f, l1 = 0.f;
    float o[8][4];
#pragma unroll
    for (int dd = 0; dd < 8; dd++)
        o[dd][0] = o[dd][1] = o[dd][2] = o[dd][3] = 0.f;

    const int rl0 = w * 16 + g, rl1 = rl0 + 8;

    for (int jt = 0; jt < NJT; jt++) {
        const int buf = jt & 1;
        const int par = (jt >> 1) & 1;
        const uint32_t* ksw = (const uint32_t*)(smc + KS_B + buf * KS_SZB);
        const uint32_t* vtw = (const uint32_t*)(smc + VT_B + buf * VT_SZB);
        const float* bsf = (const float*)(smc + BS_B + buf * BS_SZB);

        mbar_wait(buf ? mb_kv1 : mb_kv0, par);

        // ---- S = Q K^T ----
        float s_[8][4];
#pragma unroll
        for (int nn = 0; nn < 8; nn++)
            s_[nn][0] = s_[nn][1] = s_[nn][2] = s_[nn][3] = 0.f;
#pragma unroll
        for (int kk = 0; kk < 4; kk++) {
#pragma unroll
            for (int nn = 0; nn < 8; nn++) {
                const uint32_t b0 = ksw[(nn * 8 + g) * 36 + kk * 8 + t];
                const uint32_t b1 = ksw[(nn * 8 + g) * 36 + kk * 8 + t + 4];
                mma_f16(s_[nn], qa[kk][0], qa[kk][1], qa[kk][2], qa[kk][3], b0, b1);
            }
        }

        mbar_wait(buf ? mb_bs1 : mb_bs0, par);

        // ---- bias (fp32) + online softmax ----
        float mx0 = -1e30f, mx1 = -1e30f;
#pragma unroll
        for (int nn = 0; nn < 8; nn++) {
            const int c = nn * 8 + 2 * t;
            const float2 bf0 = *(const float2*)&bsf[rl0 * 68 + c];
            const float2 bf1 = *(const float2*)&bsf[rl1 * 68 + c];
            s_[nn][0] = fmaf(s_[nn][0], ATT_SCALE, bf0.x);
            s_[nn][1] = fmaf(s_[nn][1], ATT_SCALE, bf0.y);
            s_[nn][2] = fmaf(s_[nn][2], ATT_SCALE, bf1.x);
            s_[nn][3] = fmaf(s_[nn][3], ATT_SCALE, bf1.y);
            mx0 = fmaxf(mx0, fmaxf(s_[nn][0], s_[nn][1]));
            mx1 = fmaxf(mx1, fmaxf(s_[nn][2], s_[nn][3]));
        }
#pragma unroll
        for (int off = 1; off <= 2; off <<= 1) {
            mx0 = fmaxf(mx0, __shfl_xor_sync(0xffffffffu, mx0, off));
            mx1 = fmaxf(mx1, __shfl_xor_sync(0xffffffffu, mx1, off));
        }
        const float mn0 = fmaxf(m0, mx0), mn1 = fmaxf(m1, mx1);
        const float fac0 = __expf(m0 - mn0), fac1 = __expf(m1 - mn1);
        m0 = mn0; m1 = mn1;
        float rs0 = 0.f, rs1 = 0.f;
#pragma unroll
        for (int nn = 0; nn < 8; nn++) {
            s_[nn][0] = __expf(s_[nn][0] - mn0);
            s_[nn][1] = __expf(s_[nn][1] - mn0);
            s_[nn][2] = __expf(s_[nn][2] - mn1);
            s_[nn][3] = __expf(s_[nn][3] - mn1);
            rs0 += s_[nn][0] + s_[nn][1];
            rs1 += s_[nn][2] + s_[nn][3];
        }
#pragma unroll
        for (int off = 1; off <= 2; off <<= 1) {
            rs0 += __shfl_xor_sync(0xffffffffu, rs0, off);
            rs1 += __shfl_xor_sync(0xffffffffu, rs1, off);
        }
        l0 = l0 * fac0 + rs0;
        l1 = l1 * fac1 + rs1;
#pragma unroll
        for (int dd = 0; dd < 8; dd++) {
            o[dd][0] *= fac0; o[dd][1] *= fac0;
            o[dd][2] *= fac1; o[dd][3] *= fac1;
        }

        __syncthreads();   // bias buf consumed by all warps

        if (jt + 2 < NJT && tid >= 128)
            copy_bs(tid - 128, (jt + 2) << 6, buf, b, h, i0, bias32, smc,
                    buf ? mb_bs1 : mb_bs0);

        // ---- O += P V (accum frag == A frag, register cvt only) ----
#pragma unroll
        for (int jj = 0; jj < 4; jj++) {
            const uint32_t a0 = pack2h(s_[2 * jj][0], s_[2 * jj][1]);
            const uint32_t a1 = pack2h(s_[2 * jj][2], s_[2 * jj][3]);
            const uint32_t a2 = pack2h(s_[2 * jj + 1][0], s_[2 * jj + 1][1]);
            const uint32_t a3 = pack2h(s_[2 * jj + 1][2], s_[2 * jj + 1][3]);
#pragma unroll
            for (int dd = 0; dd < 8; dd++) {
                const uint32_t b0 = vtw[(dd * 8 + g) * 36 + jj * 8 + t];
                const uint32_t b1 = vtw[(dd * 8 + g) * 36 + jj * 8 + t + 4];
                mma_f16(o[dd], a0, a1, a2, a3, b0, b1);
            }
        }

        __syncthreads();   // K/V buf consumed

        if (jt + 2 < NJT && tid < 128)
            copy_kv(tid, (jt + 2) << 6, buf, b, h, k16, v16t, smc,
                    buf ? mb_kv1 : mb_kv0);
    }

    // ---- normalize + write O [b, i, h*64+d] ----
    const float inv0 = 1.0f / l0, inv1 = 1.0f / l1;
    const int row0 = i0 + rl0, row1 = i0 + rl1;
#pragma unroll
    for (int dd = 0; dd < 8; dd++) {
        const int col = h * DHH + dd * 8 + 2 * t;
        *(float2*)(obuf + (size_t)(b * NT + row0) * INNER + col) =
            make_float2(o[dd][0] * inv0, o[dd][1] * inv0);
        *(float2*)(obuf + (size_t)(b * NT + row1) * INNER + col) =
            make_float2(o[dd][2] * inv1, o[dd][3] * inv1);
    }
}

// ---------------------------------------------------------------------------
extern "C" void kernel_launch(void* const* d_in, const int* in_sizes, int n_in,
                              void* d_out, int out_size)
{
    const float* x     = (const float*)d_in[0];
    const float* cd    = (const float*)d_in[1];
    const float* Wqkv  = (const float*)d_in[2];
    const float* Wout  = (const float*)d_in[3];
    const float* bout  = (const float*)d_in[4];
    const float* rel_w = (const float*)d_in[5];
    const float* rel_b = (const float*)d_in[6];
    float* out = (float*)d_out;

    float *qkvb, *bias32, *obuf;
    __half *q16, *k16, *v16t;
    cudaGetSymbolAddress((void**)&qkvb, g_qkv);
    cudaGetSymbolAddress((void**)&bias32, g_bias32);
    cudaGetSymbolAddress((void**)&obuf, g_obuf);
    cudaGetSymbolAddress((void**)&q16, g_q16);
    cudaGetSymbolAddress((void**)&k16, g_k16);
    cudaGetSymbolAddress((void**)&v16t, g_v16t);

    cudaFuncSetAttribute(attn_kernel, cudaFuncAttributeMaxDynamicSharedMemorySize,
                         ATTN_SMEM_BYTES);

    dim3 blk(256);
    // bias32 = conv1x1(cd) per head (fp32)
    bias_kernel<<<dim3((NT * NT / 4) / 256, BB), blk>>>(cd, rel_w, rel_b, bias32);
    // qkv = x @ Wqkv (fp32)
    sgemm_kernel<false><<<dim3(QKVC / 64, (BB * NT) / 64), blk>>>(
        x, Wqkv, nullptr, qkvb, BB * NT, QKVC, DD);
    // pack to fp16 (q,k row-major; v transposed per head)
    pack_kernel<<<dim3(HH * (NT / 64), BB), blk>>>(qkvb, q16, k16, v16t);
    // fused attention
    attn_kernel<<<dim3(HH * (NT / 128), BB), blk, ATTN_SMEM_BYTES>>>(
        q16, k16, v16t, bias32, obuf);
    // out = obuf @ Wout + bout (fp32)
    sgemm_kernel<true><<<dim3(DD / 64, (BB * NT) / 64), blk>>>(
        obuf, Wout, bout, out, BB * NT, DD, DD);
}

// round 10
// speedup vs baseline: 2.5548x; 1.4640x over previous
#include <cuda_runtime.h>
#include <cuda_fp16.h>
#include <cstdint>

#define BB 4
#define NT 2048
#define DD 512
#define HH 8
#define DHH 64
#define INNER 512
#define QKVC 1536
#define ATT_SCALE 0.125f
#define NJT 32            // 2048/64 j-tiles

// Scratch (device globals — no cudaMalloc allowed)
static __device__ __half g_xhi[(size_t)BB * NT * DD];
static __device__ __half g_xlo[(size_t)BB * NT * DD];
static __device__ __half g_wqh[(size_t)QKVC * DD];   // [n][k]
static __device__ __half g_wql[(size_t)QKVC * DD];
static __device__ __half g_woh[(size_t)DD * DD];     // [n][k]
static __device__ __half g_wol[(size_t)DD * DD];
static __device__ __half g_qkv16[(size_t)BB * NT * QKVC];    // fp16 qkv
static __device__ __half g_v16t[(size_t)BB * HH * DHH * NT]; // [b,h,d,n]
static __device__ float  g_bias32[(size_t)BB * HH * NT * NT];// 537MB
static __device__ __half g_ohi[(size_t)BB * NT * INNER];
static __device__ __half g_olo[(size_t)BB * NT * INNER];

// ---------------------------------------------------------------------------
// helpers
// ---------------------------------------------------------------------------
__device__ __forceinline__ uint32_t smaddr(const void* p) {
    uint32_t a;
    asm("{.reg .u64 t; cvta.to.shared.u64 t, %1; cvt.u32.u64 %0, t;}"
        : "=r"(a) : "l"(p));
    return a;
}

__device__ __forceinline__ uint32_t pack2h(float lo, float hi) {
    uint32_t d;
    asm("cvt.rn.f16x2.f32 %0, %1, %2;" : "=r"(d) : "f"(hi), "f"(lo));
    return d;
}

__device__ __forceinline__ void mma_f16(float c[4], uint32_t a0, uint32_t a1,
                                        uint32_t a2, uint32_t a3,
                                        uint32_t b0, uint32_t b1) {
    asm volatile(
        "mma.sync.aligned.m16n8k16.row.col.f32.f16.f16.f32 "
        "{%0,%1,%2,%3}, {%4,%5,%6,%7}, {%8,%9}, {%0,%1,%2,%3};"
        : "+f"(c[0]), "+f"(c[1]), "+f"(c[2]), "+f"(c[3])
        : "r"(a0), "r"(a1), "r"(a2), "r"(a3), "r"(b0), "r"(b1));
}

__device__ __forceinline__ void bulk_cp(uint32_t dst, const void* src,
                                        uint32_t bytes, uint32_t mbar) {
    asm volatile(
        "cp.async.bulk.shared::cta.global.mbarrier::complete_tx::bytes "
        "[%0], [%1], %2, [%3];"
        :: "r"(dst), "l"(src), "r"(bytes), "r"(mbar) : "memory");
}

__device__ __forceinline__ void mbar_expect(uint32_t mbar, uint32_t bytes) {
    asm volatile("mbarrier.arrive.expect_tx.shared.b64 _, [%0], %1;"
                 :: "r"(mbar), "r"(bytes) : "memory");
}

__device__ __forceinline__ void mbar_wait(uint32_t mbar, uint32_t parity) {
    uint32_t done;
    do {
        asm volatile(
            "{.reg .pred p; "
            "mbarrier.try_wait.parity.acquire.cta.shared::cta.b64 p, [%1], %2, 0x989680; "
            "selp.b32 %0,1,0,p;}"
            : "=r"(done) : "r"(mbar), "r"(parity) : "memory");
    } while (!done);
}

// ---------------------------------------------------------------------------
// split conversion kernels
// ---------------------------------------------------------------------------
__global__ __launch_bounds__(256) void cvt_x_kernel(
    const float* __restrict__ x, __half* __restrict__ xhi,
    __half* __restrict__ xlo)
{
    const size_t i = ((size_t)blockIdx.x * 256 + threadIdx.x) * 4;
    const float4 v = *(const float4*)(x + i);
    const __half2 h0 = __float22half2_rn(make_float2(v.x, v.y));
    const __half2 h1 = __float22half2_rn(make_float2(v.z, v.w));
    const float2 f0 = __half22float2(h0);
    const float2 f1 = __half22float2(h1);
    const __half2 l0 = __float22half2_rn(make_float2(v.x - f0.x, v.y - f0.y));
    const __half2 l1 = __float22half2_rn(make_float2(v.z - f1.x, v.w - f1.y));
    *(__half2*)(xhi + i) = h0;
    *(__half2*)(xhi + i + 2) = h1;
    *(__half2*)(xlo + i) = l0;
    *(__half2*)(xlo + i + 2) = l1;
}

// W [K rows][N cols] -> wh/wl [n][k], split
__global__ __launch_bounds__(256) void cvt_w_kernel(
    const float* __restrict__ W, __half* __restrict__ wh,
    __half* __restrict__ wl, int Ncols)
{
    const int idx = blockIdx.x * 256 + threadIdx.x;
    const int n = idx >> 9, k = idx & 511;
    const float v = W[(size_t)k * Ncols + n];
    const __half h = __float2half_rn(v);
    wh[(size_t)n * DD + k] = h;
    wl[(size_t)n * DD + k] = __float2half_rn(v - __half2float(h));
}

// ---------------------------------------------------------------------------
// bias32[b,h,i,j] = sum_c rel_w[h,c]*cd[b,c,i,j] + rel_b[h]   (fp32)
// ---------------------------------------------------------------------------
__global__ __launch_bounds__(256) void bias_kernel(
    const float* __restrict__ cd, const float* __restrict__ rel_w,
    const float* __restrict__ rel_b, float* __restrict__ bias32)
{
    const int b = blockIdx.y;
    const size_t pos = (size_t)blockIdx.x * 256 + threadIdx.x;
    const int i = (int)(pos >> 9);
    const int j = (int)(pos & 511) << 2;
    const size_t NN2 = (size_t)NT * NT;
    const size_t ro = (size_t)i * NT + j;
    const float4 c0 = *(const float4*)(cd + (size_t)b * 3 * NN2 + ro);
    const float4 c1 = *(const float4*)(cd + ((size_t)b * 3 + 1) * NN2 + ro);
    const float4 c2 = *(const float4*)(cd + ((size_t)b * 3 + 2) * NN2 + ro);
#pragma unroll
    for (int h = 0; h < HH; h++) {
        const float w0 = __ldg(rel_w + h * 3 + 0);
        const float w1 = __ldg(rel_w + h * 3 + 1);
        const float w2 = __ldg(rel_w + h * 3 + 2);
        const float rb = __ldg(rel_b + h);
        float4 o;
        o.x = w0 * c0.x + w1 * c1.x + w2 * c2.x + rb;
        o.y = w0 * c0.y + w1 * c1.y + w2 * c2.y + rb;
        o.z = w0 * c0.z + w1 * c1.z + w2 * c2.z + rb;
        o.w = w0 * c0.w + w1 * c1.w + w2 * c2.w + rb;
        *(float4*)(bias32 + ((size_t)(b * HH + h) * NT + i) * NT + j) = o;
    }
}

// ---------------------------------------------------------------------------
// Split-fp16 GEMM: C = (Ahi+Alo) @ (Bhi+Blo)^T via 3 mma products.
// A [M,512] row-major hi/lo, B [N,512] row-major hi/lo (i.e. B^T of K x N).
// Tile 128x64, K-chunk 64, 256 thr, warp = 16 rows x 64 cols.
// OUT16: C fp16 (ldc halves). else: C fp32 + bias (ldc floats).
// dyn smem: AH 18432 @0, AL @18432, BH 9216 @36864, BL @46080 (55296 B)
// ---------------------------------------------------------------------------
template <bool OUT16>
__global__ __launch_bounds__(256) void hgemm3_kernel(
    const __half* __restrict__ Ahi, const __half* __restrict__ Alo,
    const __half* __restrict__ Bhi, const __half* __restrict__ Blo,
    const float* __restrict__ bias, void* __restrict__ Cv, int ldc)
{
    extern __shared__ char sh[];
    __half* AH = (__half*)sh;
    __half* AL = (__half*)(sh + 18432);
    __half* BH = (__half*)(sh + 36864);
    __half* BL = (__half*)(sh + 46080);

    const int tid = threadIdx.x;
    const int lane = tid & 31, w = tid >> 5;
    const int g = lane >> 2, t = lane & 3;
    const int m0 = blockIdx.y << 7, n0 = blockIdx.x << 6;

    float acc[8][4] = {};

    for (int kc = 0; kc < DD; kc += 64) {
#pragma unroll
        for (int i = 0; i < 4; i++) {
            const int fi = tid + (i << 8);       // 0..1023
            const int row = fi >> 3, c8 = (fi & 7) << 3;
            const size_t go = (size_t)(m0 + row) * DD + kc + c8;
            *(float4*)&AH[row * 72 + c8] = *(const float4*)(Ahi + go);
            *(float4*)&AL[row * 72 + c8] = *(const float4*)(Alo + go);
        }
#pragma unroll
        for (int i = 0; i < 2; i++) {
            const int fi = tid + (i << 8);       // 0..511
            const int row = fi >> 3, c8 = (fi & 7) << 3;
            const size_t go = (size_t)(n0 + row) * DD + kc + c8;
            *(float4*)&BH[row * 72 + c8] = *(const float4*)(Bhi + go);
            *(float4*)&BL[row * 72 + c8] = *(const float4*)(Blo + go);
        }
        __syncthreads();
        const uint32_t* ah32 = (const uint32_t*)AH;
        const uint32_t* al32 = (const uint32_t*)AL;
        const uint32_t* bh32 = (const uint32_t*)BH;
        const uint32_t* bl32 = (const uint32_t*)BL;
#pragma unroll
        for (int kk = 0; kk < 4; kk++) {
            const int i0r = (w * 16 + g) * 36 + kk * 8 + t;
            const int i1r = (w * 16 + g + 8) * 36 + kk * 8 + t;
            const uint32_t ah0 = ah32[i0r], ah1 = ah32[i1r];
            const uint32_t ah2 = ah32[i0r + 4], ah3 = ah32[i1r + 4];
            const uint32_t al0 = al32[i0r], al1 = al32[i1r];
            const uint32_t al2 = al32[i0r + 4], al3 = al32[i1r + 4];
#pragma unroll
            for (int nn = 0; nn < 8; nn++) {
                const int bi = (nn * 8 + g) * 36 + kk * 8 + t;
                const uint32_t bh0 = bh32[bi], bh1 = bh32[bi + 4];
                const uint32_t bl0 = bl32[bi], bl1 = bl32[bi + 4];
                mma_f16(acc[nn], ah0, ah1, ah2, ah3, bh0, bh1);
                mma_f16(acc[nn], ah0, ah1, ah2, ah3, bl0, bl1);
                mma_f16(acc[nn], al0, al1, al2, al3, bh0, bh1);
            }
        }
        __syncthreads();
    }

    const int row0 = m0 + w * 16 + g, row1 = row0 + 8;
    if (OUT16) {
        __half* C = (__half*)Cv;
#pragma unroll
        for (int nn = 0; nn < 8; nn++) {
            const int col = n0 + nn * 8 + 2 * t;
            *(uint32_t*)(C + (size_t)row0 * ldc + col) = pack2h(acc[nn][0], acc[nn][1]);
            *(uint32_t*)(C + (size_t)row1 * ldc + col) = pack2h(acc[nn][2], acc[nn][3]);
        }
    } else {
        float* C = (float*)Cv;
#pragma unroll
        for (int nn = 0; nn < 8; nn++) {
            const int col = n0 + nn * 8 + 2 * t;
            const float2 bb = *(const float2*)(bias + col);
            *(float2*)(C + (size_t)row0 * ldc + col) =
                make_float2(acc[nn][0] + bb.x, acc[nn][1] + bb.y);
            *(float2*)(C + (size_t)row1 * ldc + col) =
                make_float2(acc[nn][2] + bb.x, acc[nn][3] + bb.y);
        }
    }
}

// ---------------------------------------------------------------------------
// V transpose: qkv16 v-part -> v16t [b,h,d,n]
// ---------------------------------------------------------------------------
__global__ __launch_bounds__(256) void vtrans_kernel(
    const __half* __restrict__ qkv16, __half* __restrict__ v16t)
{
    __shared__ __half vs[64 * 72];
    const int tid = threadIdx.x;
    const int h = blockIdx.x & 7;
    const int n0 = (blockIdx.x >> 3) << 6;
    const int b = blockIdx.y;

#pragma unroll
    for (int it = 0; it < 8; it++) {
        const int idx = tid + (it << 8);
        const int j = idx >> 5, d2 = (idx & 31) << 1;
        const __half2 v = *(const __half2*)(qkv16
            + (size_t)(b * NT + n0 + j) * QKVC + 2 * INNER + h * DHH + d2);
        vs[d2 * 72 + j] = __low2half(v);
        vs[(d2 + 1) * 72 + j] = __high2half(v);
    }
    __syncthreads();
#pragma unroll
    for (int it = 0; it < 8; it++) {
        const int idx = tid + (it << 8);
        const int d = idx >> 5, j2 = (idx & 31) << 1;
        *(uint32_t*)(v16t + ((size_t)((b * HH + h) * DHH + d)) * NT + n0 + j2) =
            *(const uint32_t*)&vs[d * 72 + j2];
    }
}

// ---------------------------------------------------------------------------
// Fused flash attention (R8-proven), epilogue writes split hi/lo fp16 O.
// smem: KS 2x9216 @0, VT 2x9216 @18432, BS 2x34816 @36864, mbar @106496
// ---------------------------------------------------------------------------
#define KS_B 0
#define KS_SZB 9216
#define VT_B 18432
#define VT_SZB 9216
#define BS_B 36864
#define BS_SZB 34816
#define MB_B 106496
#define ATTN_SMEM_BYTES 106528

__device__ __forceinline__ void copy_kv(int idx, int jn, int buf, int b, int h,
                                        const __half* qkv16, const __half* v16t,
                                        char* smc, uint32_t mbar) {
    mbar_expect(mbar, 128u);
    if (idx < 64) {
        const __half* src = qkv16 + (size_t)(b * NT + jn + idx) * QKVC
                            + INNER + h * DHH;
        bulk_cp(smaddr(smc + KS_B + buf * KS_SZB + idx * 144), src, 128u, mbar);
    } else {
        const int r = idx - 64;
        const __half* src = v16t + ((size_t)((b * HH + h) * DHH + r)) * NT + jn;
        bulk_cp(smaddr(smc + VT_B + buf * VT_SZB + r * 144), src, 128u, mbar);
    }
}

__device__ __forceinline__ void copy_bs(int idx, int jn, int buf, int b, int h,
                                        int i0, const float* bias32,
                                        char* smc, uint32_t mbar) {
    mbar_expect(mbar, 256u);
    const float* src = bias32 + ((size_t)(b * HH + h) * NT + i0 + idx) * NT + jn;
    bulk_cp(smaddr(smc + BS_B + buf * BS_SZB + idx * 272), src, 256u, mbar);
}

__global__ __launch_bounds__(256, 2) void attn_kernel(
    const __half* __restrict__ qkv16, const __half* __restrict__ v16t,
    const float* __restrict__ bias32, __half* __restrict__ ohi,
    __half* __restrict__ olo)
{
    extern __shared__ char smc[];
    const int tid = threadIdx.x;
    const int lane = tid & 31, w = tid >> 5;
    const int g = lane >> 2, t = lane & 3;
    const int h = blockIdx.x & 7;
    const int i0 = (blockIdx.x >> 3) << 7;
    const int b = blockIdx.y;

    const uint32_t mb_kv0 = smaddr(smc + MB_B);
    const uint32_t mb_kv1 = mb_kv0 + 8;
    const uint32_t mb_bs0 = mb_kv0 + 16;
    const uint32_t mb_bs1 = mb_kv0 + 24;

    if (tid == 0) {
        asm volatile("mbarrier.init.shared.b64 [%0], %1;" :: "r"(mb_kv0), "r"(128u) : "memory");
        asm volatile("mbarrier.init.shared.b64 [%0], %1;" :: "r"(mb_kv1), "r"(128u) : "memory");
        asm volatile("mbarrier.init.shared.b64 [%0], %1;" :: "r"(mb_bs0), "r"(128u) : "memory");
        asm volatile("mbarrier.init.shared.b64 [%0], %1;" :: "r"(mb_bs1), "r"(128u) : "memory");
        asm volatile("fence.proxy.async.shared::cta;" ::: "memory");
    }
    __syncthreads();

    if (tid < 128) {
        copy_kv(tid, 0, 0, b, h, qkv16, v16t, smc, mb_kv0);
        copy_kv(tid, 64, 1, b, h, qkv16, v16t, smc, mb_kv1);
    } else {
        copy_bs(tid - 128, 0, 0, b, h, i0, bias32, smc, mb_bs0);
        copy_bs(tid - 128, 64, 1, b, h, i0, bias32, smc, mb_bs1);
    }

    // ---- Q A-fragments from qkv16 ----
    uint32_t qa[4][4];
#pragma unroll
    for (int kk = 0; kk < 4; kk++)
#pragma unroll
        for (int r = 0; r < 4; r++) {
            const int row = i0 + w * 16 + g + ((r & 1) ? 8 : 0);
            const int col = h * DHH + kk * 16 + 2 * t + ((r & 2) ? 8 : 0);
            qa[kk][r] = *(const uint32_t*)(qkv16 + (size_t)(b * NT + row) * QKVC + col);
        }

    float m0 = -1e30f, m1 = -1e30f, l0 = 0.f, l1 = 0.f;
    float o[8][4];
#pragma unroll
    for (int dd = 0; dd < 8; dd++)
        o[dd][0] = o[dd][1] = o[dd][2] = o[dd][3] = 0.f;

    const int rl0 = w * 16 + g, rl1 = rl0 + 8;

    for (int jt = 0; jt < NJT; jt++) {
        const int buf = jt & 1;
        const int par = (jt >> 1) & 1;
        const uint32_t* ksw = (const uint32_t*)(smc + KS_B + buf * KS_SZB);
        const uint32_t* vtw = (const uint32_t*)(smc + VT_B + buf * VT_SZB);
        const float* bsf = (const float*)(smc + BS_B + buf * BS_SZB);

        mbar_wait(buf ? mb_kv1 : mb_kv0, par);

        float s_[8][4];
#pragma unroll
        for (int nn = 0; nn < 8; nn++)
            s_[nn][0] = s_[nn][1] = s_[nn][2] = s_[nn][3] = 0.f;
#pragma unroll
        for (int kk = 0; kk < 4; kk++) {
#pragma unroll
            for (int nn = 0; nn < 8; nn++) {
                const uint32_t b0 = ksw[(nn * 8 + g) * 36 + kk * 8 + t];
                const uint32_t b1 = ksw[(nn * 8 + g) * 36 + kk * 8 + t + 4];
                mma_f16(s_[nn], qa[kk][0], qa[kk][1], qa[kk][2], qa[kk][3], b0, b1);
            }
        }

        mbar_wait(buf ? mb_bs1 : mb_bs0, par);

        float mx0 = -1e30f, mx1 = -1e30f;
#pragma unroll
        for (int nn = 0; nn < 8; nn++) {
            const int c = nn * 8 + 2 * t;
            const float2 bf0 = *(const float2*)&bsf[rl0 * 68 + c];
            const float2 bf1 = *(const float2*)&bsf[rl1 * 68 + c];
            s_[nn][0] = fmaf(s_[nn][0], ATT_SCALE, bf0.x);
            s_[nn][1] = fmaf(s_[nn][1], ATT_SCALE, bf0.y);
            s_[nn][2] = fmaf(s_[nn][2], ATT_SCALE, bf1.x);
            s_[nn][3] = fmaf(s_[nn][3], ATT_SCALE, bf1.y);
            mx0 = fmaxf(mx0, fmaxf(s_[nn][0], s_[nn][1]));
            mx1 = fmaxf(mx1, fmaxf(s_[nn][2], s_[nn][3]));
        }
#pragma unroll
        for (int off = 1; off <= 2; off <<= 1) {
            mx0 = fmaxf(mx0, __shfl_xor_sync(0xffffffffu, mx0, off));
            mx1 = fmaxf(mx1, __shfl_xor_sync(0xffffffffu, mx1, off));
        }
        const float mn0 = fmaxf(m0, mx0), mn1 = fmaxf(m1, mx1);
        const float fac0 = __expf(m0 - mn0), fac1 = __expf(m1 - mn1);
        m0 = mn0; m1 = mn1;
        float rs0 = 0.f, rs1 = 0.f;
#pragma unroll
        for (int nn = 0; nn < 8; nn++) {
            s_[nn][0] = __expf(s_[nn][0] - mn0);
            s_[nn][1] = __expf(s_[nn][1] - mn0);
            s_[nn][2] = __expf(s_[nn][2] - mn1);
            s_[nn][3] = __expf(s_[nn][3] - mn1);
            rs0 += s_[nn][0] + s_[nn][1];
            rs1 += s_[nn][2] + s_[nn][3];
        }
#pragma unroll
        for (int off = 1; off <= 2; off <<= 1) {
            rs0 += __shfl_xor_sync(0xffffffffu, rs0, off);
            rs1 += __shfl_xor_sync(0xffffffffu, rs1, off);
        }
        l0 = l0 * fac0 + rs0;
        l1 = l1 * fac1 + rs1;
#pragma unroll
        for (int dd = 0; dd < 8; dd++) {
            o[dd][0] *= fac0; o[dd][1] *= fac0;
            o[dd][2] *= fac1; o[dd][3] *= fac1;
        }

        __syncthreads();

        if (jt + 2 < NJT && tid >= 128)
            copy_bs(tid - 128, (jt + 2) << 6, buf, b, h, i0, bias32, smc,
                    buf ? mb_bs1 : mb_bs0);

#pragma unroll
        for (int jj = 0; jj < 4; jj++) {
            const uint32_t a0 = pack2h(s_[2 * jj][0], s_[2 * jj][1]);
            const uint32_t a1 = pack2h(s_[2 * jj][2], s_[2 * jj][3]);
            const uint32_t a2 = pack2h(s_[2 * jj + 1][0], s_[2 * jj + 1][1]);
            const uint32_t a3 = pack2h(s_[2 * jj + 1][2], s_[2 * jj + 1][3]);
#pragma unroll
            for (int dd = 0; dd < 8; dd++) {
                const uint32_t b0 = vtw[(dd * 8 + g) * 36 + jj * 8 + t];
                const uint32_t b1 = vtw[(dd * 8 + g) * 36 + jj * 8 + t + 4];
                mma_f16(o[dd], a0, a1, a2, a3, b0, b1);
            }
        }

        __syncthreads();

        if (jt + 2 < NJT && tid < 128)
            copy_kv(tid, (jt + 2) << 6, buf, b, h, qkv16, v16t, smc,
                    buf ? mb_kv1 : mb_kv0);
    }

    // ---- normalize + split-write O hi/lo ----
    const float inv0 = 1.0f / l0, inv1 = 1.0f / l1;
    const int row0 = i0 + rl0, row1 = i0 + rl1;
#pragma unroll
    for (int dd = 0; dd < 8; dd++) {
        const int col = h * DHH + dd * 8 + 2 * t;
        const float v00 = o[dd][0] * inv0, v01 = o[dd][1] * inv0;
        const float v10 = o[dd][2] * inv1, v11 = o[dd][3] * inv1;
        const __half2 h0 = __float22half2_rn(make_float2(v00, v01));
        const __half2 h1 = __float22half2_rn(make_float2(v10, v11));
        const float2 hf0 = __half22float2(h0);
        const float2 hf1 = __half22float2(h1);
        const __half2 q0 = __float22half2_rn(make_float2(v00 - hf0.x, v01 - hf0.y));
        const __half2 q1 = __float22half2_rn(make_float2(v10 - hf1.x, v11 - hf1.y));
        *(__half2*)(ohi + (size_t)(b * NT + row0) * INNER + col) = h0;
        *(__half2*)(ohi + (size_t)(b * NT + row1) * INNER + col) = h1;
        *(__half2*)(olo + (size_t)(b * NT + row0) * INNER + col) = q0;
        *(__half2*)(olo + (size_t)(b * NT + row1) * INNER + col) = q1;
    }
}

// ---------------------------------------------------------------------------
extern "C" void kernel_launch(void* const* d_in, const int* in_sizes, int n_in,
                              void* d_out, int out_size)
{
    const float* x     = (const float*)d_in[0];
    const float* cd    = (const float*)d_in[1];
    const float* Wqkv  = (const float*)d_in[2];
    const float* Wout  = (const float*)d_in[3];
    const float* bout  = (const float*)d_in[4];
    const float* rel_w = (const float*)d_in[5];
    const float* rel_b = (const float*)d_in[6];
    float* out = (float*)d_out;

    __half *xhi, *xlo, *wqh, *wql, *woh, *wol, *qkv16, *v16t, *ohi, *olo;
    float *bias32;
    cudaGetSymbolAddress((void**)&xhi, g_xhi);
    cudaGetSymbolAddress((void**)&xlo, g_xlo);
    cudaGetSymbolAddress((void**)&wqh, g_wqh);
    cudaGetSymbolAddress((void**)&wql, g_wql);
    cudaGetSymbolAddress((void**)&woh, g_woh);
    cudaGetSymbolAddress((void**)&wol, g_wol);
    cudaGetSymbolAddress((void**)&qkv16, g_qkv16);
    cudaGetSymbolAddress((void**)&v16t, g_v16t);
    cudaGetSymbolAddress((void**)&bias32, g_bias32);
    cudaGetSymbolAddress((void**)&ohi, g_ohi);
    cudaGetSymbolAddress((void**)&olo, g_olo);

    cudaFuncSetAttribute(attn_kernel, cudaFuncAttributeMaxDynamicSharedMemorySize,
                         ATTN_SMEM_BYTES);
    cudaFuncSetAttribute(hgemm3_kernel<true>,
                         cudaFuncAttributeMaxDynamicSharedMemorySize, 55296);
    cudaFuncSetAttribute(hgemm3_kernel<false>,
                         cudaFuncAttributeMaxDynamicSharedMemorySize, 55296);

    dim3 blk(256);
    // bias32 = conv1x1(cd) per head (fp32)
    bias_kernel<<<dim3((NT * NT / 4) / 256, BB), blk>>>(cd, rel_w, rel_b, bias32);
    // split x and weights to hi/lo fp16
    cvt_x_kernel<<<(BB * NT * DD) / (256 * 4), blk>>>(x, xhi, xlo);
    cvt_w_kernel<<<(QKVC * DD) / 256, blk>>>(Wqkv, wqh, wql, QKVC);
    cvt_w_kernel<<<(DD * DD) / 256, blk>>>(Wout, woh, wol, DD);
    // qkv16 = x @ Wqkv  (split-fp16, fp32-accurate, fp16 out)
    hgemm3_kernel<true><<<dim3(QKVC / 64, (BB * NT) / 128), blk, 55296>>>(
        xhi, xlo, wqh, wql, nullptr, qkv16, QKVC);
    // v transpose per head
    vtrans_kernel<<<dim3(HH * (NT / 64), BB), blk>>>(qkv16, v16t);
    // fused attention -> split O
    attn_kernel<<<dim3(HH * (NT / 128), BB), blk, ATTN_SMEM_BYTES>>>(
        qkv16, v16t, bias32, ohi, olo);
    // out = O @ Wout + bout  (split-fp16, fp32 out)
    hgemm3_kernel<false><<<dim3(DD / 64, (BB * NT) / 128), blk, 55296>>>(
        ohi, olo, woh, wol, bout, out, DD);
}

// round 12
// speedup vs baseline: 2.6480x; 1.0365x over previous
#include <cuda_runtime.h>
#include <cuda_fp16.h>
#include <cstdint>

#define BB 4
#define NT 2048
#define DD 512
#define HH 8
#define DHH 64
#define INNER 512
#define QKVC 1536
#define NJT 32            // 2048/64 j-tiles
#define L2E 1.44269504f
#define SCALE_L2E (0.125f * 1.44269504f)

// Scratch (device globals — no cudaMalloc allowed)
static __device__ __half g_xhi[(size_t)BB * NT * DD];
static __device__ __half g_xlo[(size_t)BB * NT * DD];
static __device__ __half g_wqh[(size_t)QKVC * DD];   // [n][k]
static __device__ __half g_wql[(size_t)QKVC * DD];
static __device__ __half g_woh[(size_t)DD * DD];     // [n][k]
static __device__ __half g_wol[(size_t)DD * DD];
static __device__ __half g_qkv16[(size_t)BB * NT * QKVC];    // fp16 qkv
static __device__ __half g_v16t[(size_t)BB * HH * DHH * NT]; // [b,h,d,n]
static __device__ float  g_bias32[(size_t)BB * HH * NT * NT];// bias*log2e fp32
static __device__ __half g_ohi[(size_t)BB * NT * INNER];
static __device__ __half g_olo[(size_t)BB * NT * INNER];

// ---------------------------------------------------------------------------
// helpers
// ---------------------------------------------------------------------------
__device__ __forceinline__ uint32_t smaddr(const void* p) {
    uint32_t a;
    asm("{.reg .u64 t; cvta.to.shared.u64 t, %1; cvt.u32.u64 %0, t;}"
        : "=r"(a) : "l"(p));
    return a;
}

__device__ __forceinline__ uint32_t pack2h(float lo, float hi) {
    uint32_t d;
    asm("cvt.rn.f16x2.f32 %0, %1, %2;" : "=r"(d) : "f"(hi), "f"(lo));
    return d;
}

__device__ __forceinline__ float ex2f(float x) {
    float y;
    asm("ex2.approx.f32 %0, %1;" : "=f"(y) : "f"(x));
    return y;
}

__device__ __forceinline__ void mma_f16(float c[4], uint32_t a0, uint32_t a1,
                                        uint32_t a2, uint32_t a3,
                                        uint32_t b0, uint32_t b1) {
    asm volatile(
        "mma.sync.aligned.m16n8k16.row.col.f32.f16.f16.f32 "
        "{%0,%1,%2,%3}, {%4,%5,%6,%7}, {%8,%9}, {%0,%1,%2,%3};"
        : "+f"(c[0]), "+f"(c[1]), "+f"(c[2]), "+f"(c[3])
        : "r"(a0), "r"(a1), "r"(a2), "r"(a3), "r"(b0), "r"(b1));
}

__device__ __forceinline__ void bulk_cp(uint32_t dst, const void* src,
                                        uint32_t bytes, uint32_t mbar) {
    asm volatile(
        "cp.async.bulk.shared::cta.global.mbarrier::complete_tx::bytes "
        "[%0], [%1], %2, [%3];"
        :: "r"(dst), "l"(src), "r"(bytes), "r"(mbar) : "memory");
}

__device__ __forceinline__ void mbar_expect(uint32_t mbar, uint32_t bytes) {
    asm volatile("mbarrier.arrive.expect_tx.shared.b64 _, [%0], %1;"
                 :: "r"(mbar), "r"(bytes) : "memory");
}

__device__ __forceinline__ void mbar_wait(uint32_t mbar, uint32_t parity) {
    uint32_t done;
    do {
        asm volatile(
            "{.reg .pred p; "
            "mbarrier.try_wait.parity.acquire.cta.shared::cta.b64 p, [%1], %2, 0x989680; "
            "selp.b32 %0,1,0,p;}"
            : "=r"(done) : "r"(mbar), "r"(parity) : "memory");
    } while (!done);
}

// ---------------------------------------------------------------------------
// split conversion kernels
// ---------------------------------------------------------------------------
__global__ __launch_bounds__(256) void cvt_x_kernel(
    const float* __restrict__ x, __half* __restrict__ xhi,
    __half* __restrict__ xlo)
{
    const size_t i = ((size_t)blockIdx.x * 256 + threadIdx.x) * 4;
    const float4 v = *(const float4*)(x + i);
    const __half2 h0 = __float22half2_rn(make_float2(v.x, v.y));
    const __half2 h1 = __float22half2_rn(make_float2(v.z, v.w));
    const float2 f0 = __half22float2(h0);
    const float2 f1 = __half22float2(h1);
    const __half2 l0 = __float22half2_rn(make_float2(v.x - f0.x, v.y - f0.y));
    const __half2 l1 = __float22half2_rn(make_float2(v.z - f1.x, v.w - f1.y));
    *(__half2*)(xhi + i) = h0;
    *(__half2*)(xhi + i + 2) = h1;
    *(__half2*)(xlo + i) = l0;
    *(__half2*)(xlo + i + 2) = l1;
}

// W [K rows][N cols] -> wh/wl [n][k], split
__global__ __launch_bounds__(256) void cvt_w_kernel(
    const float* __restrict__ W, __half* __restrict__ wh,
    __half* __restrict__ wl, int Ncols)
{
    const int idx = blockIdx.x * 256 + threadIdx.x;
    const int n = idx >> 9, k = idx & 511;
    const float v = W[(size_t)k * Ncols + n];
    const __half h = __float2half_rn(v);
    wh[(size_t)n * DD + k] = h;
    wl[(size_t)n * DD + k] = __float2half_rn(v - __half2float(h));
}

// ---------------------------------------------------------------------------
// bias32[b,h,i,j] = (sum_c rel_w[h,c]*cd[b,c,i,j] + rel_b[h]) * log2e  (fp32)
// ---------------------------------------------------------------------------
__global__ __launch_bounds__(256) void bias_kernel(
    const float* __restrict__ cd, const float* __restrict__ rel_w,
    const float* __restrict__ rel_b, float* __restrict__ bias32)
{
    const int b = blockIdx.y;
    const size_t pos = (size_t)blockIdx.x * 256 + threadIdx.x;
    const int i = (int)(pos >> 9);
    const int j = (int)(pos & 511) << 2;
    const size_t NN2 = (size_t)NT * NT;
    const size_t ro = (size_t)i * NT + j;
    const float4 c0 = *(const float4*)(cd + (size_t)b * 3 * NN2 + ro);
    const float4 c1 = *(const float4*)(cd + ((size_t)b * 3 + 1) * NN2 + ro);
    const float4 c2 = *(const float4*)(cd + ((size_t)b * 3 + 2) * NN2 + ro);
#pragma unroll
    for (int h = 0; h < HH; h++) {
        const float w0 = __ldg(rel_w + h * 3 + 0) * L2E;
        const float w1 = __ldg(rel_w + h * 3 + 1) * L2E;
        const float w2 = __ldg(rel_w + h * 3 + 2) * L2E;
        const float rb = __ldg(rel_b + h) * L2E;
        float4 o;
        o.x = w0 * c0.x + w1 * c1.x + w2 * c2.x + rb;
        o.y = w0 * c0.y + w1 * c1.y + w2 * c2.y + rb;
        o.z = w0 * c0.z + w1 * c1.z + w2 * c2.z + rb;
        o.w = w0 * c0.w + w1 * c1.w + w2 * c2.w + rb;
        *(float4*)(bias32 + ((size_t)(b * HH + h) * NT + i) * NT + j) = o;
    }
}

// ---------------------------------------------------------------------------
// Split-fp16 GEMM (R10-proven): C = (Ahi+Alo) @ (Bhi+Blo)^T via 3 mma.
// Tile 128x64, K-chunk 64, 256 thr, warp = 16 rows x 64 cols.
// dyn smem: AH 18432 @0, AL @18432, BH 9216 @36864, BL @46080 (55296 B)
// ---------------------------------------------------------------------------
template <bool OUT16>
__global__ __launch_bounds__(256) void hgemm3_kernel(
    const __half* __restrict__ Ahi, const __half* __restrict__ Alo,
    const __half* __restrict__ Bhi, const __half* __restrict__ Blo,
    const float* __restrict__ bias, void* __restrict__ Cv, int ldc)
{
    extern __shared__ char sh[];
    __half* AH = (__half*)sh;
    __half* AL = (__half*)(sh + 18432);
    __half* BH = (__half*)(sh + 36864);
    __half* BL = (__half*)(sh + 46080);

    const int tid = threadIdx.x;
    const int lane = tid & 31, w = tid >> 5;
    const int g = lane >> 2, t = lane & 3;
    const int m0 = blockIdx.y << 7, n0 = blockIdx.x << 6;

    float acc[8][4] = {};

    for (int kc = 0; kc < DD; kc += 64) {
#pragma unroll
        for (int i = 0; i < 4; i++) {
            const int fi = tid + (i << 8);
            const int row = fi >> 3, c8 = (fi & 7) << 3;
            const size_t go = (size_t)(m0 + row) * DD + kc + c8;
            *(float4*)&AH[row * 72 + c8] = *(const float4*)(Ahi + go);
            *(float4*)&AL[row * 72 + c8] = *(const float4*)(Alo + go);
        }
#pragma unroll
        for (int i = 0; i < 2; i++) {
            const int fi = tid + (i << 8);
            const int row = fi >> 3, c8 = (fi & 7) << 3;
            const size_t go = (size_t)(n0 + row) * DD + kc + c8;
            *(float4*)&BH[row * 72 + c8] = *(const float4*)(Bhi + go);
            *(float4*)&BL[row * 72 + c8] = *(const float4*)(Blo + go);
        }
        __syncthreads();
        const uint32_t* ah32 = (const uint32_t*)AH;
        const uint32_t* al32 = (const uint32_t*)AL;
        const uint32_t* bh32 = (const uint32_t*)BH;
        const uint32_t* bl32 = (const uint32_t*)BL;
#pragma unroll
        for (int kk = 0; kk < 4; kk++) {
            const int i0r = (w * 16 + g) * 36 + kk * 8 + t;
            const int i1r = (w * 16 + g + 8) * 36 + kk * 8 + t;
            const uint32_t ah0 = ah32[i0r], ah1 = ah32[i1r];
            const uint32_t ah2 = ah32[i0r + 4], ah3 = ah32[i1r + 4];
            const uint32_t al0 = al32[i0r], al1 = al32[i1r];
            const uint32_t al2 = al32[i0r + 4], al3 = al32[i1r + 4];
#pragma unroll
            for (int nn = 0; nn < 8; nn++) {
                const int bi = (nn * 8 + g) * 36 + kk * 8 + t;
                const uint32_t bh0 = bh32[bi], bh1 = bh32[bi + 4];
                const uint32_t bl0 = bl32[bi], bl1 = bl32[bi + 4];
                mma_f16(acc[nn], ah0, ah1, ah2, ah3, bh0, bh1);
                mma_f16(acc[nn], ah0, ah1, ah2, ah3, bl0, bl1);
                mma_f16(acc[nn], al0, al1, al2, al3, bh0, bh1);
            }
        }
        __syncthreads();
    }

    const int row0 = m0 + w * 16 + g, row1 = row0 + 8;
    if (OUT16) {
        __half* C = (__half*)Cv;
#pragma unroll
        for (int nn = 0; nn < 8; nn++) {
            const int col = n0 + nn * 8 + 2 * t;
            *(uint32_t*)(C + (size_t)row0 * ldc + col) = pack2h(acc[nn][0], acc[nn][1]);
            *(uint32_t*)(C + (size_t)row1 * ldc + col) = pack2h(acc[nn][2], acc[nn][3]);
        }
    } else {
        float* C = (float*)Cv;
#pragma unroll
        for (int nn = 0; nn < 8; nn++) {
            const int col = n0 + nn * 8 + 2 * t;
            const float2 bb = *(const float2*)(bias + col);
            *(float2*)(C + (size_t)row0 * ldc + col) =
                make_float2(acc[nn][0] + bb.x, acc[nn][1] + bb.y);
            *(float2*)(C + (size_t)row1 * ldc + col) =
                make_float2(acc[nn][2] + bb.x, acc[nn][3] + bb.y);
        }
    }
}

// ---------------------------------------------------------------------------
// V transpose: qkv16 v-part -> v16t [b,h,d,n]
// ---------------------------------------------------------------------------
__global__ __launch_bounds__(256) void vtrans_kernel(
    const __half* __restrict__ qkv16, __half* __restrict__ v16t)
{
    __shared__ __half vs[64 * 72];
    const int tid = threadIdx.x;
    const int h = blockIdx.x & 7;
    const int n0 = (blockIdx.x >> 3) << 6;
    const int b = blockIdx.y;

#pragma unroll
    for (int it = 0; it < 8; it++) {
        const int idx = tid + (it << 8);
        const int j = idx >> 5, d2 = (idx & 31) << 1;
        const __half2 v = *(const __half2*)(qkv16
            + (size_t)(b * NT + n0 + j) * QKVC + 2 * INNER + h * DHH + d2);
        vs[d2 * 72 + j] = __low2half(v);
        vs[(d2 + 1) * 72 + j] = __high2half(v);
    }
    __syncthreads();
#pragma unroll
    for (int it = 0; it < 8; it++) {
        const int idx = tid + (it << 8);
        const int d = idx >> 5, j2 = (idx & 31) << 1;
        *(uint32_t*)(v16t + ((size_t)((b * HH + h) * DHH + d)) * NT + n0 + j2) =
            *(const uint32_t*)&vs[d * 72 + j2];
    }
}

// ---------------------------------------------------------------------------
// Fused flash attention: log2-domain softmax, deferred l-reduction,
// single sync per tile, fp32 bias (premultiplied by log2e).
// smem: KS 2x9216 @0, VT 2x9216 @18432, BS 2x34816 @36864, mbar @106496
// ---------------------------------------------------------------------------
#define KS_B 0
#define KS_SZB 9216
#define VT_B 18432
#define VT_SZB 9216
#define BS_B 36864
#define BS_SZB 34816
#define MB_B 106496
#define ATTN_SMEM_BYTES 106528

__device__ __forceinline__ void copy_kv(int idx, int jn, int buf, int b, int h,
                                        const __half* qkv16, const __half* v16t,
                                        char* smc, uint32_t mbar) {
    mbar_expect(mbar, 128u);
    if (idx < 64) {
        const __half* src = qkv16 + (size_t)(b * NT + jn + idx) * QKVC
                            + INNER + h * DHH;
        bulk_cp(smaddr(smc + KS_B + buf * KS_SZB + idx * 144), src, 128u, mbar);
    } else {
        const int r = idx - 64;
        const __half* src = v16t + ((size_t)((b * HH + h) * DHH + r)) * NT + jn;
        bulk_cp(smaddr(smc + VT_B + buf * VT_SZB + r * 144), src, 128u, mbar);
    }
}

__device__ __forceinline__ void copy_bs(int idx, int jn, int buf, int b, int h,
                                        int i0, const float* bias32,
                                        char* smc, uint32_t mbar) {
    mbar_expect(mbar, 256u);
    const float* src = bias32 + ((size_t)(b * HH + h) * NT + i0 + idx) * NT + jn;
    bulk_cp(smaddr(smc + BS_B + buf * BS_SZB + idx * 272), src, 256u, mbar);
}

__global__ __launch_bounds__(256, 2) void attn_kernel(
    const __half* __restrict__ qkv16, const __half* __restrict__ v16t,
    const float* __restrict__ bias32, __half* __restrict__ ohi,
    __half* __restrict__ olo)
{
    extern __shared__ char smc[];
    const int tid = threadIdx.x;
    const int lane = tid & 31, w = tid >> 5;
    const int g = lane >> 2, t = lane & 3;
    const int h = blockIdx.x & 7;
    const int i0 = (blockIdx.x >> 3) << 7;
    const int b = blockIdx.y;

    const uint32_t mb_kv0 = smaddr(smc + MB_B);
    const uint32_t mb_kv1 = mb_kv0 + 8;
    const uint32_t mb_bs0 = mb_kv0 + 16;
    const uint32_t mb_bs1 = mb_kv0 + 24;

    if (tid == 0) {
        asm volatile("mbarrier.init.shared.b64 [%0], %1;" :: "r"(mb_kv0), "r"(128u) : "memory");
        asm volatile("mbarrier.init.shared.b64 [%0], %1;" :: "r"(mb_kv1), "r"(128u) : "memory");
        asm volatile("mbarrier.init.shared.b64 [%0], %1;" :: "r"(mb_bs0), "r"(128u) : "memory");
        asm volatile("mbarrier.init.shared.b64 [%0], %1;" :: "r"(mb_bs1), "r"(128u) : "memory");
        asm volatile("fence.proxy.async.shared::cta;" ::: "memory");
    }
    __syncthreads();

    if (tid < 128) {
        copy_kv(tid, 0, 0, b, h, qkv16, v16t, smc, mb_kv0);
        copy_kv(tid, 64, 1, b, h, qkv16, v16t, smc, mb_kv1);
    } else {
        copy_bs(tid - 128, 0, 0, b, h, i0, bias32, smc, mb_bs0);
        copy_bs(tid - 128, 64, 1, b, h, i0, bias32, smc, mb_bs1);
    }

    // ---- Q A-fragments from qkv16 ----
    uint32_t qa[4][4];
#pragma unroll
    for (int kk = 0; kk < 4; kk++)
#pragma unroll
        for (int r = 0; r < 4; r++) {
            const int row = i0 + w * 16 + g + ((r & 1) ? 8 : 0);
            const int col = h * DHH + kk * 16 + 2 * t + ((r & 2) ? 8 : 0);
            qa[kk][r] = *(const uint32_t*)(qkv16 + (size_t)(b * NT + row) * QKVC + col);
        }

    float m0 = -1e30f, m1 = -1e30f, l0 = 0.f, l1 = 0.f;
    float o[8][4];
#pragma unroll
    for (int dd = 0; dd < 8; dd++)
        o[dd][0] = o[dd][1] = o[dd][2] = o[dd][3] = 0.f;

    const int rl0 = w * 16 + g, rl1 = rl0 + 8;

    for (int jt = 0; jt < NJT; jt++) {
        const int buf = jt & 1;
        const int par = (jt >> 1) & 1;
        const uint32_t* ksw = (const uint32_t*)(smc + KS_B + buf * KS_SZB);
        const uint32_t* vtw = (const uint32_t*)(smc + VT_B + buf * VT_SZB);
        const float* bsf = (const float*)(smc + BS_B + buf * BS_SZB);

        mbar_wait(buf ? mb_kv1 : mb_kv0, par);

        // ---- S = Q K^T ----
        float s_[8][4];
#pragma unroll
        for (int nn = 0; nn < 8; nn++)
            s_[nn][0] = s_[nn][1] = s_[nn][2] = s_[nn][3] = 0.f;
#pragma unroll
        for (int kk = 0; kk < 4; kk++) {
#pragma unroll
            for (int nn = 0; nn < 8; nn++) {
                const uint32_t b0 = ksw[(nn * 8 + g) * 36 + kk * 8 + t];
                const uint32_t b1 = ksw[(nn * 8 + g) * 36 + kk * 8 + t + 4];
                mma_f16(s_[nn], qa[kk][0], qa[kk][1], qa[kk][2], qa[kk][3], b0, b1);
            }
        }

        mbar_wait(buf ? mb_bs1 : mb_bs0, par);

        // ---- logits in log2 domain: x = S*scale*log2e + bias32 (pre-l2e) ----
        float mx0 = -1e30f, mx1 = -1e30f;
#pragma unroll
        for (int nn = 0; nn < 8; nn++) {
            const int c = nn * 8 + 2 * t;
            const float2 bf0 = *(const float2*)&bsf[rl0 * 68 + c];
            const float2 bf1 = *(const float2*)&bsf[rl1 * 68 + c];
            s_[nn][0] = fmaf(s_[nn][0], SCALE_L2E, bf0.x);
            s_[nn][1] = fmaf(s_[nn][1], SCALE_L2E, bf0.y);
            s_[nn][2] = fmaf(s_[nn][2], SCALE_L2E, bf1.x);
            s_[nn][3] = fmaf(s_[nn][3], SCALE_L2E, bf1.y);
            mx0 = fmaxf(mx0, fmaxf(s_[nn][0], s_[nn][1]));
            mx1 = fmaxf(mx1, fmaxf(s_[nn][2], s_[nn][3]));
        }
#pragma unroll
        for (int off = 1; off <= 2; off <<= 1) {
            mx0 = fmaxf(mx0, __shfl_xor_sync(0xffffffffu, mx0, off));
            mx1 = fmaxf(mx1, __shfl_xor_sync(0xffffffffu, mx1, off));
        }
        const float mn0 = fmaxf(m0, mx0), mn1 = fmaxf(m1, mx1);
        const float fac0 = ex2f(m0 - mn0), fac1 = ex2f(m1 - mn1);
        m0 = mn0; m1 = mn1;
        float rs0 = 0.f, rs1 = 0.f;
#pragma unroll
        for (int nn = 0; nn < 8; nn++) {
            s_[nn][0] = ex2f(s_[nn][0] - mn0);
            s_[nn][1] = ex2f(s_[nn][1] - mn0);
            s_[nn][2] = ex2f(s_[nn][2] - mn1);
            s_[nn][3] = ex2f(s_[nn][3] - mn1);
            rs0 += s_[nn][0] + s_[nn][1];
            rs1 += s_[nn][2] + s_[nn][3];
        }
        // deferred: l stays lane-partial (quad reduction in epilogue)
        l0 = l0 * fac0 + rs0;
        l1 = l1 * fac1 + rs1;
#pragma unroll
        for (int dd = 0; dd < 8; dd++) {
            o[dd][0] *= fac0; o[dd][1] *= fac0;
            o[dd][2] *= fac1; o[dd][3] *= fac1;
        }

        // ---- O += P V (accum frag == A frag, register cvt only) ----
#pragma unroll
        for (int jj = 0; jj < 4; jj++) {
            const uint32_t a0 = pack2h(s_[2 * jj][0], s_[2 * jj][1]);
            const uint32_t a1 = pack2h(s_[2 * jj][2], s_[2 * jj][3]);
            const uint32_t a2 = pack2h(s_[2 * jj + 1][0], s_[2 * jj + 1][1]);
            const uint32_t a3 = pack2h(s_[2 * jj + 1][2], s_[2 * jj + 1][3]);
#pragma unroll
            for (int dd = 0; dd < 8; dd++) {
                const uint32_t b0 = vtw[(dd * 8 + g) * 36 + jj * 8 + t];
                const uint32_t b1 = vtw[(dd * 8 + g) * 36 + jj * 8 + t + 4];
                mma_f16(o[dd], a0, a1, a2, a3, b0, b1);
            }
        }

        __syncthreads();   // KV + bias buffers fully consumed by all warps

        if (jt + 2 < NJT) {
            const int jn = (jt + 2) << 6;
            if (tid < 128)
                copy_kv(tid, jn, buf, b, h, qkv16, v16t, smc,
                        buf ? mb_kv1 : mb_kv0);
            else
                copy_bs(tid - 128, jn, buf, b, h, i0, bias32, smc,
                        buf ? mb_bs1 : mb_bs0);
        }
    }

    // ---- epilogue: quad-reduce l, normalize + split-write O hi/lo ----
    l0 += __shfl_xor_sync(0xffffffffu, l0, 1);
    l0 += __shfl_xor_sync(0xffffffffu, l0, 2);
    l1 += __shfl_xor_sync(0xffffffffu, l1, 1);
    l1 += __shfl_xor_sync(0xffffffffu, l1, 2);
    const float inv0 = 1.0f / l0, inv1 = 1.0f / l1;
    const int row0 = i0 + rl0, row1 = i0 + rl1;
#pragma unroll
    for (int dd = 0; dd < 8; dd++) {
        const int col = h * DHH + dd * 8 + 2 * t;
        const float v00 = o[dd][0] * inv0, v01 = o[dd][1] * inv0;
        const float v10 = o[dd][2] * inv1, v11 = o[dd][3] * inv1;
        const __half2 h0 = __float22half2_rn(make_float2(v00, v01));
        const __half2 h1 = __float22half2_rn(make_float2(v10, v11));
        const float2 hf0 = __half22float2(h0);
        const float2 hf1 = __half22float2(h1);
        const __half2 q0 = __float22half2_rn(make_float2(v00 - hf0.x, v01 - hf0.y));
        const __half2 q1 = __float22half2_rn(make_float2(v10 - hf1.x, v11 - hf1.y));
        *(__half2*)(ohi + (size_t)(b * NT + row0) * INNER + col) = h0;
        *(__half2*)(ohi + (size_t)(b * NT + row1) * INNER + col) = h1;
        *(__half2*)(olo + (size_t)(b * NT + row0) * INNER + col) = q0;
        *(__half2*)(olo + (size_t)(b * NT + row1) * INNER + col) = q1;
    }
}

// ---------------------------------------------------------------------------
extern "C" void kernel_launch(void* const* d_in, const int* in_sizes, int n_in,
                              void* d_out, int out_size)
{
    const float* x     = (const float*)d_in[0];
    const float* cd    = (const float*)d_in[1];
    const float* Wqkv  = (const float*)d_in[2];
    const float* Wout  = (const float*)d_in[3];
    const float* bout  = (const float*)d_in[4];
    const float* rel_w = (const float*)d_in[5];
    const float* rel_b = (const float*)d_in[6];
    float* out = (float*)d_out;

    __half *xhi, *xlo, *wqh, *wql, *woh, *wol, *qkv16, *v16t, *ohi, *olo;
    float *bias32;
    cudaGetSymbolAddress((void**)&xhi, g_xhi);
    cudaGetSymbolAddress((void**)&xlo, g_xlo);
    cudaGetSymbolAddress((void**)&wqh, g_wqh);
    cudaGetSymbolAddress((void**)&wql, g_wql);
    cudaGetSymbolAddress((void**)&woh, g_woh);
    cudaGetSymbolAddress((void**)&wol, g_wol);
    cudaGetSymbolAddress((void**)&qkv16, g_qkv16);
    cudaGetSymbolAddress((void**)&v16t, g_v16t);
    cudaGetSymbolAddress((void**)&bias32, g_bias32);
    cudaGetSymbolAddress((void**)&ohi, g_ohi);
    cudaGetSymbolAddress((void**)&olo, g_olo);

    cudaFuncSetAttribute(attn_kernel, cudaFuncAttributeMaxDynamicSharedMemorySize,
                         ATTN_SMEM_BYTES);
    cudaFuncSetAttribute(hgemm3_kernel<true>,
                         cudaFuncAttributeMaxDynamicSharedMemorySize, 55296);
    cudaFuncSetAttribute(hgemm3_kernel<false>,
                         cudaFuncAttributeMaxDynamicSharedMemorySize, 55296);

    dim3 blk(256);
    // bias32 = conv1x1(cd) per head, premultiplied by log2e (fp32)
    bias_kernel<<<dim3((NT * NT / 4) / 256, BB), blk>>>(cd, rel_w, rel_b, bias32);
    // split x and weights to hi/lo fp16
    cvt_x_kernel<<<(BB * NT * DD) / (256 * 4), blk>>>(x, xhi, xlo);
    cvt_w_kernel<<<(QKVC * DD) / 256, blk>>>(Wqkv, wqh, wql, QKVC);
    cvt_w_kernel<<<(DD * DD) / 256, blk>>>(Wout, woh, wol, DD);
    // qkv16 = x @ Wqkv  (split-fp16, fp32-accurate, fp16 out)
    hgemm3_kernel<true><<<dim3(QKVC / 64, (BB * NT) / 128), blk, 55296>>>(
        xhi, xlo, wqh, wql, nullptr, qkv16, QKVC);
    // v transpose per head
    vtrans_kernel<<<dim3(HH * (NT / 64), BB), blk>>>(qkv16, v16t);
    // fused attention -> split O
    attn_kernel<<<dim3(HH * (NT / 128), BB), blk, ATTN_SMEM_BYTES>>>(
        qkv16, v16t, bias32, ohi, olo);
    // out = O @ Wout + bout  (split-fp16, fp32 out)
    hgemm3_kernel<false><<<dim3(DD / 64, (BB * NT) / 128), blk, 55296>>>(
        ohi, olo, woh, wol, bout, out, DD);
}

// round 13
// speedup vs baseline: 2.7787x; 1.0494x over previous
#include <cuda_runtime.h>
#include <cuda_fp16.h>
#include <cstdint>

#define BB 4
#define NT 2048
#define DD 512
#define HH 8
#define DHH 64
#define INNER 512
#define QKVC 1536
#define NJT 32            // 2048/64 j-tiles
#define L2E 1.44269504f
#define SCALE_L2E (0.125f * 1.44269504f)

// Scratch (device globals — no cudaMalloc allowed)
static __device__ __half g_xhi[(size_t)BB * NT * DD];
static __device__ __half g_xlo[(size_t)BB * NT * DD];
static __device__ __half g_wqh[(size_t)QKVC * DD];   // [n][k]
static __device__ __half g_wql[(size_t)QKVC * DD];
static __device__ __half g_woh[(size_t)DD * DD];     // [n][k]
static __device__ __half g_wol[(size_t)DD * DD];
static __device__ __half g_qkv16[(size_t)BB * NT * QKVC];    // fp16 qkv
static __device__ __half g_v16t[(size_t)BB * HH * DHH * NT]; // [b,h,d,n]
static __device__ float  g_bias32[(size_t)BB * HH * NT * NT];// bias*log2e fp32
static __device__ __half g_ohi[(size_t)BB * NT * INNER];
static __device__ __half g_olo[(size_t)BB * NT * INNER];

// ---------------------------------------------------------------------------
// helpers
// ---------------------------------------------------------------------------
__device__ __forceinline__ uint32_t smaddr(const void* p) {
    uint32_t a;
    asm("{.reg .u64 t; cvta.to.shared.u64 t, %1; cvt.u32.u64 %0, t;}"
        : "=r"(a) : "l"(p));
    return a;
}

__device__ __forceinline__ uint32_t pack2h(float lo, float hi) {
    uint32_t d;
    asm("cvt.rn.f16x2.f32 %0, %1, %2;" : "=r"(d) : "f"(hi), "f"(lo));
    return d;
}

__device__ __forceinline__ float ex2f(float x) {
    float y;
    asm("ex2.approx.f32 %0, %1;" : "=f"(y) : "f"(x));
    return y;
}

__device__ __forceinline__ void mma_f16(float c[4], uint32_t a0, uint32_t a1,
                                        uint32_t a2, uint32_t a3,
                                        uint32_t b0, uint32_t b1) {
    asm volatile(
        "mma.sync.aligned.m16n8k16.row.col.f32.f16.f16.f32 "
        "{%0,%1,%2,%3}, {%4,%5,%6,%7}, {%8,%9}, {%0,%1,%2,%3};"
        : "+f"(c[0]), "+f"(c[1]), "+f"(c[2]), "+f"(c[3])
        : "r"(a0), "r"(a1), "r"(a2), "r"(a3), "r"(b0), "r"(b1));
}

__device__ __forceinline__ void bulk_cp(uint32_t dst, const void* src,
                                        uint32_t bytes, uint32_t mbar) {
    asm volatile(
        "cp.async.bulk.shared::cta.global.mbarrier::complete_tx::bytes "
        "[%0], [%1], %2, [%3];"
        :: "r"(dst), "l"(src), "r"(bytes), "r"(mbar) : "memory");
}

__device__ __forceinline__ void mbar_expect(uint32_t mbar, uint32_t bytes) {
    asm volatile("mbarrier.arrive.expect_tx.shared.b64 _, [%0], %1;"
                 :: "r"(mbar), "r"(bytes) : "memory");
}

__device__ __forceinline__ void mbar_wait(uint32_t mbar, uint32_t parity) {
    uint32_t done;
    do {
        asm volatile(
            "{.reg .pred p; "
            "mbarrier.try_wait.parity.acquire.cta.shared::cta.b64 p, [%1], %2, 0x989680; "
            "selp.b32 %0,1,0,p;}"
            : "=r"(done) : "r"(mbar), "r"(parity) : "memory");
    } while (!done);
}

// ---------------------------------------------------------------------------
// split conversion kernels
// ---------------------------------------------------------------------------
__global__ __launch_bounds__(256) void cvt_x_kernel(
    const float* __restrict__ x, __half* __restrict__ xhi,
    __half* __restrict__ xlo)
{
    const size_t i = ((size_t)blockIdx.x * 256 + threadIdx.x) * 4;
    const float4 v = *(const float4*)(x + i);
    const __half2 h0 = __float22half2_rn(make_float2(v.x, v.y));
    const __half2 h1 = __float22half2_rn(make_float2(v.z, v.w));
    const float2 f0 = __half22float2(h0);
    const float2 f1 = __half22float2(h1);
    const __half2 l0 = __float22half2_rn(make_float2(v.x - f0.x, v.y - f0.y));
    const __half2 l1 = __float22half2_rn(make_float2(v.z - f1.x, v.w - f1.y));
    *(__half2*)(xhi + i) = h0;
    *(__half2*)(xhi + i + 2) = h1;
    *(__half2*)(xlo + i) = l0;
    *(__half2*)(xlo + i + 2) = l1;
}

// W [K rows][N cols] -> wh/wl [n][k], split
__global__ __launch_bounds__(256) void cvt_w_kernel(
    const float* __restrict__ W, __half* __restrict__ wh,
    __half* __restrict__ wl, int Ncols)
{
    const int idx = blockIdx.x * 256 + threadIdx.x;
    const int n = idx >> 9, k = idx & 511;
    const float v = W[(size_t)k * Ncols + n];
    const __half h = __float2half_rn(v);
    wh[(size_t)n * DD + k] = h;
    wl[(size_t)n * DD + k] = __float2half_rn(v - __half2float(h));
}

// ---------------------------------------------------------------------------
// bias body: bias32[b,h,i,j] = (sum_c rel_w[h,c]*cd[...] + rel_b[h]) * log2e
// ---------------------------------------------------------------------------
__device__ __forceinline__ void bias_body(
    int bid, const float* __restrict__ cd, const float* __restrict__ rel_w,
    const float* __restrict__ rel_b, float* __restrict__ bias32)
{
    const int b = bid >> 12;                       // 4096 blocks per batch
    const size_t pos = (size_t)(bid & 4095) * 256 + threadIdx.x;
    const int i = (int)(pos >> 9);
    const int j = (int)(pos & 511) << 2;
    const size_t NN2 = (size_t)NT * NT;
    const size_t ro = (size_t)i * NT + j;
    const float4 c0 = *(const float4*)(cd + (size_t)b * 3 * NN2 + ro);
    const float4 c1 = *(const float4*)(cd + ((size_t)b * 3 + 1) * NN2 + ro);
    const float4 c2 = *(const float4*)(cd + ((size_t)b * 3 + 2) * NN2 + ro);
#pragma unroll
    for (int h = 0; h < HH; h++) {
        const float w0 = __ldg(rel_w + h * 3 + 0) * L2E;
        const float w1 = __ldg(rel_w + h * 3 + 1) * L2E;
        const float w2 = __ldg(rel_w + h * 3 + 2) * L2E;
        const float rb = __ldg(rel_b + h) * L2E;
        float4 o;
        o.x = w0 * c0.x + w1 * c1.x + w2 * c2.x + rb;
        o.y = w0 * c0.y + w1 * c1.y + w2 * c2.y + rb;
        o.z = w0 * c0.z + w1 * c1.z + w2 * c2.z + rb;
        o.w = w0 * c0.w + w1 * c1.w + w2 * c2.w + rb;
        *(float4*)(bias32 + ((size_t)(b * HH + h) * NT + i) * NT + j) = o;
    }
}

// ---------------------------------------------------------------------------
// Split-fp16 GEMM body (R10-proven): C = (Ahi+Alo)@(Bhi+Blo)^T via 3 mma.
// Tile 128x64, K-chunk 64, 256 thr.
// dyn smem: AH 18432 @0, AL @18432, BH 9216 @36864, BL @46080 (55296 B)
// ---------------------------------------------------------------------------
template <bool OUT16>
__device__ __forceinline__ void hgemm3_body(
    const __half* __restrict__ Ahi, const __half* __restrict__ Alo,
    const __half* __restrict__ Bhi, const __half* __restrict__ Blo,
    const float* __restrict__ bias, void* __restrict__ Cv, int ldc,
    int bx, int by, char* sh)
{
    __half* AH = (__half*)sh;
    __half* AL = (__half*)(sh + 18432);
    __half* BH = (__half*)(sh + 36864);
    __half* BL = (__half*)(sh + 46080);

    const int tid = threadIdx.x;
    const int lane = tid & 31, w = tid >> 5;
    const int g = lane >> 2, t = lane & 3;
    const int m0 = by << 7, n0 = bx << 6;

    float acc[8][4] = {};

    for (int kc = 0; kc < DD; kc += 64) {
#pragma unroll
        for (int i = 0; i < 4; i++) {
            const int fi = tid + (i << 8);
            const int row = fi >> 3, c8 = (fi & 7) << 3;
            const size_t go = (size_t)(m0 + row) * DD + kc + c8;
            *(float4*)&AH[row * 72 + c8] = *(const float4*)(Ahi + go);
            *(float4*)&AL[row * 72 + c8] = *(const float4*)(Alo + go);
        }
#pragma unroll
        for (int i = 0; i < 2; i++) {
            const int fi = tid + (i << 8);
            const int row = fi >> 3, c8 = (fi & 7) << 3;
            const size_t go = (size_t)(n0 + row) * DD + kc + c8;
            *(float4*)&BH[row * 72 + c8] = *(const float4*)(Bhi + go);
            *(float4*)&BL[row * 72 + c8] = *(const float4*)(Blo + go);
        }
        __syncthreads();
        const uint32_t* ah32 = (const uint32_t*)AH;
        const uint32_t* al32 = (const uint32_t*)AL;
        const uint32_t* bh32 = (const uint32_t*)BH;
        const uint32_t* bl32 = (const uint32_t*)BL;
#pragma unroll
        for (int kk = 0; kk < 4; kk++) {
            const int i0r = (w * 16 + g) * 36 + kk * 8 + t;
            const int i1r = (w * 16 + g + 8) * 36 + kk * 8 + t;
            const uint32_t ah0 = ah32[i0r], ah1 = ah32[i1r];
            const uint32_t ah2 = ah32[i0r + 4], ah3 = ah32[i1r + 4];
            const uint32_t al0 = al32[i0r], al1 = al32[i1r];
            const uint32_t al2 = al32[i0r + 4], al3 = al32[i1r + 4];
#pragma unroll
            for (int nn = 0; nn < 8; nn++) {
                const int bi = (nn * 8 + g) * 36 + kk * 8 + t;
                const uint32_t bh0 = bh32[bi], bh1 = bh32[bi + 4];
                const uint32_t bl0 = bl32[bi], bl1 = bl32[bi + 4];
                mma_f16(acc[nn], ah0, ah1, ah2, ah3, bh0, bh1);
                mma_f16(acc[nn], ah0, ah1, ah2, ah3, bl0, bl1);
                mma_f16(acc[nn], al0, al1, al2, al3, bh0, bh1);
            }
        }
        __syncthreads();
    }

    const int row0 = m0 + w * 16 + g, row1 = row0 + 8;
    if (OUT16) {
        __half* C = (__half*)Cv;
#pragma unroll
        for (int nn = 0; nn < 8; nn++) {
            const int col = n0 + nn * 8 + 2 * t;
            *(uint32_t*)(C + (size_t)row0 * ldc + col) = pack2h(acc[nn][0], acc[nn][1]);
            *(uint32_t*)(C + (size_t)row1 * ldc + col) = pack2h(acc[nn][2], acc[nn][3]);
        }
    } else {
        float* C = (float*)Cv;
#pragma unroll
        for (int nn = 0; nn < 8; nn++) {
            const int col = n0 + nn * 8 + 2 * t;
            const float2 bb = *(const float2*)(bias + col);
            *(float2*)(C + (size_t)row0 * ldc + col) =
                make_float2(acc[nn][0] + bb.x, acc[nn][1] + bb.y);
            *(float2*)(C + (size_t)row1 * ldc + col) =
                make_float2(acc[nn][2] + bb.x, acc[nn][3] + bb.y);
        }
    }
}

// ---------------------------------------------------------------------------
// Fused front-end: qkv GEMM blocks interleaved with bias blocks (Bresenham
// stripe g(i)=i*3/35 keeps both pipe classes resident on every SM).
// 1536 gemm blocks + 16384 bias blocks = 17920 total.
// ---------------------------------------------------------------------------
#define FUSED_TOTAL 17920
#define GEMM_BLOCKS 1536

__global__ __launch_bounds__(256) void fused_pre_kernel(
    const float* __restrict__ cd, const float* __restrict__ rel_w,
    const float* __restrict__ rel_b, float* __restrict__ bias32,
    const __half* __restrict__ xhi, const __half* __restrict__ xlo,
    const __half* __restrict__ wqh, const __half* __restrict__ wql,
    __half* __restrict__ qkv16)
{
    extern __shared__ char sh[];
    const int i = blockIdx.x;
    const int gi  = (i * 3) / 35;        // gemm blocks before i
    const int gi1 = ((i + 1) * 3) / 35;
    if (gi1 > gi && gi < GEMM_BLOCKS) {
        // GEMM block: gid = gi; bx = gid % 24, by = gid / 24
        hgemm3_body<true>(xhi, xlo, wqh, wql, nullptr, qkv16, QKVC,
                          gi % 24, gi / 24, sh);
    } else {
        // bias block
        const int bid = i - gi1;
        if (bid < 16384)
            bias_body(bid, cd, rel_w, rel_b, bias32);
    }
}

// standalone hgemm3 (out-projection)
template <bool OUT16>
__global__ __launch_bounds__(256) void hgemm3_kernel(
    const __half* __restrict__ Ahi, const __half* __restrict__ Alo,
    const __half* __restrict__ Bhi, const __half* __restrict__ Blo,
    const float* __restrict__ bias, void* __restrict__ Cv, int ldc)
{
    extern __shared__ char sh[];
    hgemm3_body<OUT16>(Ahi, Alo, Bhi, Blo, bias, Cv, ldc,
                       blockIdx.x, blockIdx.y, sh);
}

// ---------------------------------------------------------------------------
// V transpose: qkv16 v-part -> v16t [b,h,d,n]
// ---------------------------------------------------------------------------
__global__ __launch_bounds__(256) void vtrans_kernel(
    const __half* __restrict__ qkv16, __half* __restrict__ v16t)
{
    __shared__ __half vs[64 * 72];
    const int tid = threadIdx.x;
    const int h = blockIdx.x & 7;
    const int n0 = (blockIdx.x >> 3) << 6;
    const int b = blockIdx.y;

#pragma unroll
    for (int it = 0; it < 8; it++) {
        const int idx = tid + (it << 8);
        const int j = idx >> 5, d2 = (idx & 31) << 1;
        const __half2 v = *(const __half2*)(qkv16
            + (size_t)(b * NT + n0 + j) * QKVC + 2 * INNER + h * DHH + d2);
        vs[d2 * 72 + j] = __low2half(v);
        vs[(d2 + 1) * 72 + j] = __high2half(v);
    }
    __syncthreads();
#pragma unroll
    for (int it = 0; it < 8; it++) {
        const int idx = tid + (it << 8);
        const int d = idx >> 5, j2 = (idx & 31) << 1;
        *(uint32_t*)(v16t + ((size_t)((b * HH + h) * DHH + d)) * NT + n0 + j2) =
            *(const uint32_t*)&vs[d * 72 + j2];
    }
}

// ---------------------------------------------------------------------------
// Fused flash attention (R12-proven): log2-domain softmax, deferred l-
// reduction, single sync per tile, fp32 bias (premultiplied by log2e).
// smem: KS 2x9216 @0, VT 2x9216 @18432, BS 2x34816 @36864, mbar @106496
// ---------------------------------------------------------------------------
#define KS_B 0
#define KS_SZB 9216
#define VT_B 18432
#define VT_SZB 9216
#define BS_B 36864
#define BS_SZB 34816
#define MB_B 106496
#define ATTN_SMEM_BYTES 106528

__device__ __forceinline__ void copy_kv(int idx, int jn, int buf, int b, int h,
                                        const __half* qkv16, const __half* v16t,
                                        char* smc, uint32_t mbar) {
    mbar_expect(mbar, 128u);
    if (idx < 64) {
        const __half* src = qkv16 + (size_t)(b * NT + jn + idx) * QKVC
                            + INNER + h * DHH;
        bulk_cp(smaddr(smc + KS_B + buf * KS_SZB + idx * 144), src, 128u, mbar);
    } else {
        const int r = idx - 64;
        const __half* src = v16t + ((size_t)((b * HH + h) * DHH + r)) * NT + jn;
        bulk_cp(smaddr(smc + VT_B + buf * VT_SZB + r * 144), src, 128u, mbar);
    }
}

__device__ __forceinline__ void copy_bs(int idx, int jn, int buf, int b, int h,
                                        int i0, const float* bias32,
                                        char* smc, uint32_t mbar) {
    mbar_expect(mbar, 256u);
    const float* src = bias32 + ((size_t)(b * HH + h) * NT + i0 + idx) * NT + jn;
    bulk_cp(smaddr(smc + BS_B + buf * BS_SZB + idx * 272), src, 256u, mbar);
}

__global__ __launch_bounds__(256, 2) void attn_kernel(
    const __half* __restrict__ qkv16, const __half* __restrict__ v16t,
    const float* __restrict__ bias32, __half* __restrict__ ohi,
    __half* __restrict__ olo)
{
    extern __shared__ char smc[];
    const int tid = threadIdx.x;
    const int lane = tid & 31, w = tid >> 5;
    const int g = lane >> 2, t = lane & 3;
    const int h = blockIdx.x & 7;
    const int i0 = (blockIdx.x >> 3) << 7;
    const int b = blockIdx.y;

    const uint32_t mb_kv0 = smaddr(smc + MB_B);
    const uint32_t mb_kv1 = mb_kv0 + 8;
    const uint32_t mb_bs0 = mb_kv0 + 16;
    const uint32_t mb_bs1 = mb_kv0 + 24;

    if (tid == 0) {
        asm volatile("mbarrier.init.shared.b64 [%0], %1;" :: "r"(mb_kv0), "r"(128u) : "memory");
        asm volatile("mbarrier.init.shared.b64 [%0], %1;" :: "r"(mb_kv1), "r"(128u) : "memory");
        asm volatile("mbarrier.init.shared.b64 [%0], %1;" :: "r"(mb_bs0), "r"(128u) : "memory");
        asm volatile("mbarrier.init.shared.b64 [%0], %1;" :: "r"(mb_bs1), "r"(128u) : "memory");
        asm volatile("fence.proxy.async.shared::cta;" ::: "memory");
    }
    __syncthreads();

    if (tid < 128) {
        copy_kv(tid, 0, 0, b, h, qkv16, v16t, smc, mb_kv0);
        copy_kv(tid, 64, 1, b, h, qkv16, v16t, smc, mb_kv1);
    } else {
        copy_bs(tid - 128, 0, 0, b, h, i0, bias32, smc, mb_bs0);
        copy_bs(tid - 128, 64, 1, b, h, i0, bias32, smc, mb_bs1);
    }

    // ---- Q A-fragments from qkv16 ----
    uint32_t qa[4][4];
#pragma unroll
    for (int kk = 0; kk < 4; kk++)
#pragma unroll
        for (int r = 0; r < 4; r++) {
            const int row = i0 + w * 16 + g + ((r & 1) ? 8 : 0);
            const int col = h * DHH + kk * 16 + 2 * t + ((r & 2) ? 8 : 0);
            qa[kk][r] = *(const uint32_t*)(qkv16 + (size_t)(b * NT + row) * QKVC + col);
        }

    float m0 = -1e30f, m1 = -1e30f, l0 = 0.f, l1 = 0.f;
    float o[8][4];
#pragma unroll
    for (int dd = 0; dd < 8; dd++)
        o[dd][0] = o[dd][1] = o[dd][2] = o[dd][3] = 0.f;

    const int rl0 = w * 16 + g, rl1 = rl0 + 8;

    for (int jt = 0; jt < NJT; jt++) {
        const int buf = jt & 1;
        const int par = (jt >> 1) & 1;
        const uint32_t* ksw = (const uint32_t*)(smc + KS_B + buf * KS_SZB);
        const uint32_t* vtw = (const uint32_t*)(smc + VT_B + buf * VT_SZB);
        const float* bsf = (const float*)(smc + BS_B + buf * BS_SZB);

        mbar_wait(buf ? mb_kv1 : mb_kv0, par);

        // ---- S = Q K^T ----
        float s_[8][4];
#pragma unroll
        for (int nn = 0; nn < 8; nn++)
            s_[nn][0] = s_[nn][1] = s_[nn][2] = s_[nn][3] = 0.f;
#pragma unroll
        for (int kk = 0; kk < 4; kk++) {
#pragma unroll
            for (int nn = 0; nn < 8; nn++) {
                const uint32_t b0 = ksw[(nn * 8 + g) * 36 + kk * 8 + t];
                const uint32_t b1 = ksw[(nn * 8 + g) * 36 + kk * 8 + t + 4];
                mma_f16(s_[nn], qa[kk][0], qa[kk][1], qa[kk][2], qa[kk][3], b0, b1);
            }
        }

        mbar_wait(buf ? mb_bs1 : mb_bs0, par);

        // ---- logits in log2 domain: x = S*scale*log2e + bias32 (pre-l2e) ----
        float mx0 = -1e30f, mx1 = -1e30f;
#pragma unroll
        for (int nn = 0; nn < 8; nn++) {
            const int c = nn * 8 + 2 * t;
            const float2 bf0 = *(const float2*)&bsf[rl0 * 68 + c];
            const float2 bf1 = *(const float2*)&bsf[rl1 * 68 + c];
            s_[nn][0] = fmaf(s_[nn][0], SCALE_L2E, bf0.x);
            s_[nn][1] = fmaf(s_[nn][1], SCALE_L2E, bf0.y);
            s_[nn][2] = fmaf(s_[nn][2], SCALE_L2E, bf1.x);
            s_[nn][3] = fmaf(s_[nn][3], SCALE_L2E, bf1.y);
            mx0 = fmaxf(mx0, fmaxf(s_[nn][0], s_[nn][1]));
            mx1 = fmaxf(mx1, fmaxf(s_[nn][2], s_[nn][3]));
        }
#pragma unroll
        for (int off = 1; off <= 2; off <<= 1) {
            mx0 = fmaxf(mx0, __shfl_xor_sync(0xffffffffu, mx0, off));
            mx1 = fmaxf(mx1, __shfl_xor_sync(0xffffffffu, mx1, off));
        }
        const float mn0 = fmaxf(m0, mx0), mn1 = fmaxf(m1, mx1);
        const float fac0 = ex2f(m0 - mn0), fac1 = ex2f(m1 - mn1);
        m0 = mn0; m1 = mn1;
        float rs0 = 0.f, rs1 = 0.f;
#pragma unroll
        for (int nn = 0; nn < 8; nn++) {
            s_[nn][0] = ex2f(s_[nn][0] - mn0);
            s_[nn][1] = ex2f(s_[nn][1] - mn0);
            s_[nn][2] = ex2f(s_[nn][2] - mn1);
            s_[nn][3] = ex2f(s_[nn][3] - mn1);
            rs0 += s_[nn][0] + s_[nn][1];
            rs1 += s_[nn][2] + s_[nn][3];
        }
        // deferred: l stays lane-partial (quad reduction in epilogue)
        l0 = l0 * fac0 + rs0;
        l1 = l1 * fac1 + rs1;
#pragma unroll
        for (int dd = 0; dd < 8; dd++) {
            o[dd][0] *= fac0; o[dd][1] *= fac0;
            o[dd][2] *= fac1; o[dd][3] *= fac1;
        }

        // ---- O += P V (accum frag == A frag, register cvt only) ----
#pragma unroll
        for (int jj = 0; jj < 4; jj++) {
            const uint32_t a0 = pack2h(s_[2 * jj][0], s_[2 * jj][1]);
            const uint32_t a1 = pack2h(s_[2 * jj][2], s_[2 * jj][3]);
            const uint32_t a2 = pack2h(s_[2 * jj + 1][0], s_[2 * jj + 1][1]);
            const uint32_t a3 = pack2h(s_[2 * jj + 1][2], s_[2 * jj + 1][3]);
#pragma unroll
            for (int dd = 0; dd < 8; dd++) {
                const uint32_t b0 = vtw[(dd * 8 + g) * 36 + jj * 8 + t];
                const uint32_t b1 = vtw[(dd * 8 + g) * 36 + jj * 8 + t + 4];
                mma_f16(o[dd], a0, a1, a2, a3, b0, b1);
            }
        }

        __syncthreads();   // KV + bias buffers fully consumed by all warps

        if (jt + 2 < NJT) {
            const int jn = (jt + 2) << 6;
            if (tid < 128)
                copy_kv(tid, jn, buf, b, h, qkv16, v16t, smc,
                        buf ? mb_kv1 : mb_kv0);
            else
                copy_bs(tid - 128, jn, buf, b, h, i0, bias32, smc,
                        buf ? mb_bs1 : mb_bs0);
        }
    }

    // ---- epilogue: quad-reduce l, normalize + split-write O hi/lo ----
    l0 += __shfl_xor_sync(0xffffffffu, l0, 1);
    l0 += __shfl_xor_sync(0xffffffffu, l0, 2);
    l1 += __shfl_xor_sync(0xffffffffu, l1, 1);
    l1 += __shfl_xor_sync(0xffffffffu, l1, 2);
    const float inv0 = 1.0f / l0, inv1 = 1.0f / l1;
    const int row0 = i0 + rl0, row1 = i0 + rl1;
#pragma unroll
    for (int dd = 0; dd < 8; dd++) {
        const int col = h * DHH + dd * 8 + 2 * t;
        const float v00 = o[dd][0] * inv0, v01 = o[dd][1] * inv0;
        const float v10 = o[dd][2] * inv1, v11 = o[dd][3] * inv1;
        const __half2 h0 = __float22half2_rn(make_float2(v00, v01));
        const __half2 h1 = __float22half2_rn(make_float2(v10, v11));
        const float2 hf0 = __half22float2(h0);
        const float2 hf1 = __half22float2(h1);
        const __half2 q0 = __float22half2_rn(make_float2(v00 - hf0.x, v01 - hf0.y));
        const __half2 q1 = __float22half2_rn(make_float2(v10 - hf1.x, v11 - hf1.y));
        *(__half2*)(ohi + (size_t)(b * NT + row0) * INNER + col) = h0;
        *(__half2*)(ohi + (size_t)(b * NT + row1) * INNER + col) = h1;
        *(__half2*)(olo + (size_t)(b * NT + row0) * INNER + col) = q0;
        *(__half2*)(olo + (size_t)(b * NT + row1) * INNER + col) = q1;
    }
}

// ---------------------------------------------------------------------------
extern "C" void kernel_launch(void* const* d_in, const int* in_sizes, int n_in,
                              void* d_out, int out_size)
{
    const float* x     = (const float*)d_in[0];
    const float* cd    = (const float*)d_in[1];
    const float* Wqkv  = (const float*)d_in[2];
    const float* Wout  = (const float*)d_in[3];
    const float* bout  = (const float*)d_in[4];
    const float* rel_w = (const float*)d_in[5];
    const float* rel_b = (const float*)d_in[6];
    float* out = (float*)d_out;

    __half *xhi, *xlo, *wqh, *wql, *woh, *wol, *qkv16, *v16t, *ohi, *olo;
    float *bias32;
    cudaGetSymbolAddress((void**)&xhi, g_xhi);
    cudaGetSymbolAddress((void**)&xlo, g_xlo);
    cudaGetSymbolAddress((void**)&wqh, g_wqh);
    cudaGetSymbolAddress((void**)&wql, g_wql);
    cudaGetSymbolAddress((void**)&woh, g_woh);
    cudaGetSymbolAddress((void**)&wol, g_wol);
    cudaGetSymbolAddress((void**)&qkv16, g_qkv16);
    cudaGetSymbolAddress((void**)&v16t, g_v16t);
    cudaGetSymbolAddress((void**)&bias32, g_bias32);
    cudaGetSymbolAddress((void**)&ohi, g_ohi);
    cudaGetSymbolAddress((void**)&olo, g_olo);

    cudaFuncSetAttribute(attn_kernel, cudaFuncAttributeMaxDynamicSharedMemorySize,
                         ATTN_SMEM_BYTES);
    cudaFuncSetAttribute(fused_pre_kernel,
                         cudaFuncAttributeMaxDynamicSharedMemorySize, 55296);
    cudaFuncSetAttribute(hgemm3_kernel<false>,
                         cudaFuncAttributeMaxDynamicSharedMemorySize, 55296);

    dim3 blk(256);
    // split x and weights to hi/lo fp16
    cvt_x_kernel<<<(BB * NT * DD) / (256 * 4), blk>>>(x, xhi, xlo);
    cvt_w_kernel<<<(QKVC * DD) / 256, blk>>>(Wqkv, wqh, wql, QKVC);
    cvt_w_kernel<<<(DD * DD) / 256, blk>>>(Wout, woh, wol, DD);
    // fused: bias32 (conv1x1 * log2e) blocks interleaved with qkv GEMM blocks
    fused_pre_kernel<<<FUSED_TOTAL, blk, 55296>>>(
        cd, rel_w, rel_b, bias32, xhi, xlo, wqh, wql, qkv16);
    // v transpose per head
    vtrans_kernel<<<dim3(HH * (NT / 64), BB), blk>>>(qkv16, v16t);
    // fused attention -> split O
    attn_kernel<<<dim3(HH * (NT / 128), BB), blk, ATTN_SMEM_BYTES>>>(
        qkv16, v16t, bias32, ohi, olo);
    // out = O @ Wout + bout  (split-fp16, fp32 out)
    hgemm3_kernel<false><<<dim3(DD / 64, (BB * NT) / 128), blk, 55296>>>(
        ohi, olo, woh, wol, bout, out, DD);
}